// round 14
// baseline (speedup 1.0000x reference)
#include <cuda_runtime.h>
#include <cuda_fp16.h>
#include <math.h>
#include <stdint.h>

// ---------------- Problem constants ----------------
#define T_SEQ   2048
#define HID     5120
#define NH      16
#define D_NOPE  128
#define D_ROPE  64
#define D_V     128
#define Q_LORA  1536
#define KV_LORA 512
#define QK_HD   (D_NOPE + D_ROPE)   // 192
#define KVA_N   (KV_LORA + D_ROPE)  // 576
#define KVA_NP  640
#define QKV_N   (Q_LORA + KVA_NP)   // 2176 = 17 * 128
#define QB_N    (NH * QK_HD)        // 3072
#define KVB_N   (NH * (D_NOPE + D_V)) // 4096
#define O_K     (NH * D_V)          // 2048

static const float SCALE = 0.07216878364870322f; // 192^-0.5
#define EPS_RMS 1e-6f

typedef __half f16;

// ---------------- Scratch ----------------
__device__ float g_qkv  [T_SEQ * QKV_N];        // [qa(1536) | kv(576) | pad]

__device__ f16 g_hs    [T_SEQ * HID];
__device__ f16 g_qc    [T_SEQ * Q_LORA];
__device__ f16 g_kvc   [T_SEQ * KV_LORA];
__device__ f16 g_qf    [(long)NH*T_SEQ*QK_HD];  // roped Q (G3 epilogue)
__device__ f16 g_kf    [(long)NH*T_SEQ*QK_HD];  // K (G4 epi + kpe)
__device__ f16 g_v     [(long)NH*T_SEQ*D_V];    // V (G4 epilogue)
__device__ f16 g_at    [T_SEQ * O_K];

// ---------------- helpers ----------------
__device__ __forceinline__ uint32_t smem_u32(const void* p) {
    return (uint32_t)__cvta_generic_to_shared(p);
}
__device__ __forceinline__ void cp16(uint32_t dst, const void* src) {
    asm volatile("cp.async.cg.shared.global [%0], [%1], 16;\n" :: "r"(dst), "l"(src));
}
__device__ __forceinline__ void cp_commit() {
    asm volatile("cp.async.commit_group;\n");
}
template<int NMAX>
__device__ __forceinline__ void cp_wait() {
    asm volatile("cp.async.wait_group %0;\n" :: "n"(NMAX));
}
__device__ __forceinline__ void ldsm_x4(uint32_t addr, uint32_t r[4]) {
    asm volatile("ldmatrix.sync.aligned.m8n8.x4.shared.b16 {%0,%1,%2,%3}, [%4];"
                 : "=r"(r[0]), "=r"(r[1]), "=r"(r[2]), "=r"(r[3]) : "r"(addr));
}
__device__ __forceinline__ void ldsm_x4_t(uint32_t addr, uint32_t r[4]) {
    asm volatile("ldmatrix.sync.aligned.m8n8.x4.trans.shared.b16 {%0,%1,%2,%3}, [%4];"
                 : "=r"(r[0]), "=r"(r[1]), "=r"(r[2]), "=r"(r[3]) : "r"(addr));
}
__device__ __forceinline__ void mma_f16(float c[4], const uint32_t a[4],
                                        uint32_t b0, uint32_t b1) {
    asm volatile(
        "mma.sync.aligned.m16n8k16.row.col.f32.f16.f16.f32 "
        "{%0,%1,%2,%3}, {%4,%5,%6,%7}, {%8,%9}, {%0,%1,%2,%3};"
        : "+f"(c[0]), "+f"(c[1]), "+f"(c[2]), "+f"(c[3])
        : "r"(a[0]), "r"(a[1]), "r"(a[2]), "r"(a[3]), "r"(b0), "r"(b1));
}
__device__ __forceinline__ uint32_t pack2(f16 a, f16 b) {
    __half2 t = __halves2half2(a, b);
    return *reinterpret_cast<uint32_t*>(&t);
}

// ---------------- NN tensor GEMM, fp32 B with fused convert, fused epilogues ----
// A: f16 [M][K] via cp.async. B: fp32, converted in-register to f16 SMEM.
// COMB=1: B spans [w_qa(1536) | w_kva(576) | zero-pad] per column.
// EPI=0: C fp32.  EPI=1: roped Q -> qf f16.  EPI=2: scatter -> kf/v f16.
#define BM 128
#define BN 128
#define BK 16
#define G_STG  10496
#define G_SMEM (4 * G_STG)

template<int EPI, int COMB>
__global__ __launch_bounds__(256)
void tgemm_nn(const f16* __restrict__ A, const float* __restrict__ B,
              const float* __restrict__ B2,
              float* __restrict__ C, f16* __restrict__ O1, f16* __restrict__ O2,
              const int* __restrict__ positions,
              int N, int K, int lda, int ldb, int ldc, float alpha)
{
    extern __shared__ char smem[];
    int row0 = blockIdx.y * BM;
    int col0 = blockIdx.x * BN;

    int tid  = threadIdx.x;
    int lane = tid & 31;
    int warp = tid >> 5;
    int wm   = warp >> 1;
    int wn   = warp & 1;

    int aRow = tid >> 1;
    int aKc  = (tid & 1) * 8;
    int bKr  = tid >> 4;
    int bNc  = (tid & 15) * 8;

    uint32_t sb = smem_u32(smem);

    // ---- B source resolution (uniform per thread) ----
    const float* bsrc;
    int  bld;
    bool bvalid = true;
    {
        int c = col0 + bNc;
        if (COMB) {
            if (c < Q_LORA) { bsrc = B + c;  bld = Q_LORA; }
            else {
                int c2 = c - Q_LORA;
                bvalid = (c2 < KVA_N);
                bsrc = B2 + c2; bld = KVA_N;
            }
        } else { bsrc = B + c; bld = ldb; }
    }

    float br[8];
    auto ldgB = [&](int i) {
        if (bvalid) {
            const float* p = bsrc + (long)(i * BK + bKr) * bld;
            float4 v0 = *reinterpret_cast<const float4*>(p);
            float4 v1 = *reinterpret_cast<const float4*>(p + 4);
            br[0] = v0.x; br[1] = v0.y; br[2] = v0.z; br[3] = v0.w;
            br[4] = v1.x; br[5] = v1.y; br[6] = v1.z; br[7] = v1.w;
        } else {
#pragma unroll
            for (int u = 0; u < 8; u++) br[u] = 0.f;
        }
    };
    auto stsB = [&](int i) {
        uint4 pk;
        pk.x = pack2(__float2half_rn(br[0]), __float2half_rn(br[1]));
        pk.y = pack2(__float2half_rn(br[2]), __float2half_rn(br[3]));
        pk.z = pack2(__float2half_rn(br[4]), __float2half_rn(br[5]));
        pk.w = pack2(__float2half_rn(br[6]), __float2half_rn(br[7]));
        *reinterpret_cast<uint4*>(smem + (i & 3) * G_STG + 6144 + (bKr * 136 + bNc) * 2) = pk;
    };
    auto issueA = [&](int i) {
        cp16(sb + (i & 3) * G_STG + (aRow * 24 + aKc) * 2,
             &A[(long)(row0 + aRow) * lda + i * BK + aKc]);
    };

    float acc[2][8][4];
#pragma unroll
    for (int i = 0; i < 2; i++)
#pragma unroll
        for (int j = 0; j < 8; j++)
#pragma unroll
            for (int q = 0; q < 4; q++) acc[i][j][q] = 0.f;

    int ntiles = K / BK;

    // Prologue: B(0) direct, B(1) in regs; A(0), A(1) via cp.async.
    ldgB(0); stsB(0);
    if (ntiles > 1) ldgB(1);
    issueA(0); cp_commit();
    if (ntiles > 1) issueA(1);
    cp_commit();

    for (int i = 0; i < ntiles; i++) {
        if (i + 1 < ntiles) stsB(i + 1);                 // regs from previous ldg
        if (i + 2 < ntiles) { ldgB(i + 2); issueA(i + 2); }
        cp_commit();
        cp_wait<2>();
        __syncthreads();

        uint32_t stg = sb + (i & 3) * G_STG;
        uint32_t a_h[2][4];
#pragma unroll
        for (int mt = 0; mt < 2; mt++) {
            int r = wm * 32 + mt * 16 + (lane & 15);
            int c = (lane >> 4) * 8;
            ldsm_x4(stg + (r * 24 + c) * 2, a_h[mt]);
        }
        int rB    = lane & 15;
        int halfB = lane >> 4;
#pragma unroll
        for (int p = 0; p < 4; p++) {
            uint32_t bh[4];
            int c = wn * 64 + p * 16 + halfB * 8;
            ldsm_x4_t(stg + 6144 + (rB * 136 + c) * 2, bh);
#pragma unroll
            for (int mt = 0; mt < 2; mt++)
#pragma unroll
                for (int j = 0; j < 2; j++)
                    mma_f16(acc[mt][2 * p + j], a_h[mt], bh[2 * j], bh[2 * j + 1]);
        }
    }

    int gid = lane >> 2, tig = lane & 3;
#pragma unroll
    for (int mt = 0; mt < 2; mt++) {
        int rb = row0 + wm * 32 + mt * 16 + gid;
#pragma unroll
        for (int nt = 0; nt < 8; nt++) {
            int c = col0 + wn * 64 + nt * 8 + tig * 2;
            if (c >= N) continue;
            float p00 = acc[mt][nt][0], p01 = acc[mt][nt][1];
            float p10 = acc[mt][nt][2], p11 = acc[mt][nt][3];
            if (EPI == 0) {
                *reinterpret_cast<float2*>(&C[(long)rb * ldc + c]) =
                    make_float2(alpha * p00, alpha * p01);
                *reinterpret_cast<float2*>(&C[(long)(rb + 8) * ldc + c]) =
                    make_float2(alpha * p10, alpha * p11);
            } else if (EPI == 1) {
                int h = c / QK_HD, d = c % QK_HD;
#pragma unroll
                for (int rr = 0; rr < 2; rr++) {
                    int r = rb + rr * 8;
                    float v0 = rr ? p10 : p00, v1 = rr ? p11 : p01;
                    long dst = ((long)h * T_SEQ + r) * QK_HD + d;
                    if (d < D_NOPE) {
                        *reinterpret_cast<uint32_t*>(&O1[dst]) =
                            pack2(__float2half_rn(v0), __float2half_rn(v1));
                    } else {
                        int i2 = (d - D_NOPE) >> 1;
                        float pos = (float)positions[r];
                        float inv = expf(-logf(10000.0f) * (2.0f * i2) / (float)D_ROPE);
                        float ang = pos * inv;
                        float cs = cosf(ang), sn = sinf(ang);
                        *reinterpret_cast<uint32_t*>(&O1[dst]) =
                            pack2(__float2half_rn(v0 * cs - v1 * sn),
                                  __float2half_rn(v1 * cs + v0 * sn));
                    }
                }
            } else {
                int h = c >> 8, d = c & 255;
#pragma unroll
                for (int rr = 0; rr < 2; rr++) {
                    int r = rb + rr * 8;
                    float v0 = rr ? p10 : p00, v1 = rr ? p11 : p01;
                    uint32_t pk = pack2(__float2half_rn(v0), __float2half_rn(v1));
                    if (d < D_NOPE)
                        *reinterpret_cast<uint32_t*>(&O1[((long)h * T_SEQ + r) * QK_HD + d]) = pk;
                    else
                        *reinterpret_cast<uint32_t*>(&O2[((long)h * T_SEQ + r) * D_V + d - D_NOPE]) = pk;
                }
            }
        }
    }
}

// ---------------- Fused flash attention (all single-plane fp16) ----------------
#define FA_QSZ   (128 * 200 * 2)
#define FA_STG   6144
#define FA_SMEM  (FA_QSZ + 4 * FA_STG)

__global__ __launch_bounds__(256)
void flash_kernel(const f16* __restrict__ qf,
                  const f16* __restrict__ kf,  const f16* __restrict__ v,
                  f16* __restrict__ at)
{
    extern __shared__ char smem[];
    int h   = blockIdx.x;
    int tid = threadIdx.x;
    int lane = tid & 31;
    int wid  = tid >> 5;
    int wrow = wid * 16;

    uint32_t sQ  = smem_u32(smem);
    uint32_t stg = sQ + FA_QSZ;

    const long hT = (long)h * T_SEQ;

    auto loadQ = [&](int i0) {
#pragma unroll
        for (int it = 0; it < 12; it++) {
            int u = it * 256 + tid;
            int row = u / 24, off = (u % 24) * 8;
            cp16(sQ + (row * 200 + off) * 2, qf + (hT + i0 + row) * QK_HD + off);
        }
    };
    auto load_chunk = [&](int c) {
        uint32_t st = stg + (c & 3) * FA_STG;
        int j = c / 20, r = c % 20;
        if (r < 12) {
            int d0 = r * 16;
            int row = tid >> 1, off = (tid & 1) * 8;
            cp16(st + (row * 24 + off) * 2, kf + (hT + j * 128 + row) * QK_HD + d0 + off);
        } else {
            int q0 = (r - 12) * 16;
            int row = tid >> 4, off = (tid & 15) * 8;
            cp16(st + (row * 136 + off) * 2, v + (hT + j * 128 + q0 + row) * D_V + off);
        }
    };

    for (int rep = 0; rep < 2; rep++) {
        int iblk = rep == 0 ? blockIdx.y : (T_SEQ / 128 - 1) - blockIdx.y;
        int i0   = iblk * 128;
        int nch  = (iblk + 1) * 20;

        float s[16][4], o[16][4];
        float m0 = -1e30f, m1 = -1e30f, l0 = 0.f, l1 = 0.f;
#pragma unroll
        for (int nt = 0; nt < 16; nt++)
#pragma unroll
            for (int q = 0; q < 4; q++) o[nt][q] = 0.f;

        __syncthreads();
        loadQ(i0);
        load_chunk(0); cp_commit();
        load_chunk(1); cp_commit();

        int lr0 = wrow + (lane >> 2);
        int lr1 = lr0 + 8;

        for (int c = 0; c < nch; c++) {
            if (c + 2 < nch) load_chunk(c + 2);
            cp_commit();
            cp_wait<2>();
            __syncthreads();

            uint32_t st = stg + (c & 3) * FA_STG;
            int j = c / 20, r = c % 20;

            if (r < 12) {
                if (r == 0) {
#pragma unroll
                    for (int nt = 0; nt < 16; nt++)
#pragma unroll
                        for (int q = 0; q < 4; q++) s[nt][q] = 0.f;
                }
                uint32_t a_h[4];
                int ar = wrow + (lane & 15);
                int ac = r * 16 + (lane >> 4) * 8;
                ldsm_x4(sQ + (ar * 200 + ac) * 2, a_h);
                int g = lane >> 3, rr = lane & 7;
                int nbase = ((g >> 1) << 3) + rr;
                int cc = (g & 1) * 8;
#pragma unroll
                for (int p = 0; p < 8; p++) {
                    uint32_t bh[4];
                    ldsm_x4(st + ((p * 16 + nbase) * 24 + cc) * 2, bh);
#pragma unroll
                    for (int jj = 0; jj < 2; jj++)
                        mma_f16(s[2 * p + jj], a_h, bh[2 * jj], bh[2 * jj + 1]);
                }
                if (r == 11) {
#pragma unroll
                    for (int nt = 0; nt < 16; nt++)
#pragma unroll
                        for (int q = 0; q < 4; q++) s[nt][q] *= SCALE;
                    if (j == iblk) {
#pragma unroll
                        for (int nt = 0; nt < 16; nt++) {
                            int c0 = nt * 8 + ((lane & 3) << 1);
                            if (c0     > lr0) s[nt][0] = -1e30f;
                            if (c0 + 1 > lr0) s[nt][1] = -1e30f;
                            if (c0     > lr1) s[nt][2] = -1e30f;
                            if (c0 + 1 > lr1) s[nt][3] = -1e30f;
                        }
                    }
                    float mr0 = -1e30f, mr1 = -1e30f;
#pragma unroll
                    for (int nt = 0; nt < 16; nt++) {
                        mr0 = fmaxf(mr0, fmaxf(s[nt][0], s[nt][1]));
                        mr1 = fmaxf(mr1, fmaxf(s[nt][2], s[nt][3]));
                    }
                    mr0 = fmaxf(mr0, __shfl_xor_sync(~0u, mr0, 1));
                    mr0 = fmaxf(mr0, __shfl_xor_sync(~0u, mr0, 2));
                    mr1 = fmaxf(mr1, __shfl_xor_sync(~0u, mr1, 1));
                    mr1 = fmaxf(mr1, __shfl_xor_sync(~0u, mr1, 2));
                    float mn0 = fmaxf(m0, mr0), mn1 = fmaxf(m1, mr1);
                    float sc0 = __expf(m0 - mn0), sc1 = __expf(m1 - mn1);
                    float rs0 = 0.f, rs1 = 0.f;
#pragma unroll
                    for (int nt = 0; nt < 16; nt++) {
                        s[nt][0] = __expf(s[nt][0] - mn0); rs0 += s[nt][0];
                        s[nt][1] = __expf(s[nt][1] - mn0); rs0 += s[nt][1];
                        s[nt][2] = __expf(s[nt][2] - mn1); rs1 += s[nt][2];
                        s[nt][3] = __expf(s[nt][3] - mn1); rs1 += s[nt][3];
                    }
                    rs0 += __shfl_xor_sync(~0u, rs0, 1); rs0 += __shfl_xor_sync(~0u, rs0, 2);
                    rs1 += __shfl_xor_sync(~0u, rs1, 1); rs1 += __shfl_xor_sync(~0u, rs1, 2);
                    l0 = l0 * sc0 + rs0;  l1 = l1 * sc1 + rs1;
                    m0 = mn0; m1 = mn1;
#pragma unroll
                    for (int nt = 0; nt < 16; nt++) {
                        o[nt][0] *= sc0; o[nt][1] *= sc0;
                        o[nt][2] *= sc1; o[nt][3] *= sc1;
                    }
                }
            } else {
                int q = r - 12;
                uint32_t ah[4];
                {
                    const float* t0 = s[2 * q];
                    const float* t1 = s[2 * q + 1];
                    ah[0] = pack2(__float2half_rn(t0[0]), __float2half_rn(t0[1]));
                    ah[1] = pack2(__float2half_rn(t0[2]), __float2half_rn(t0[3]));
                    ah[2] = pack2(__float2half_rn(t1[0]), __float2half_rn(t1[1]));
                    ah[3] = pack2(__float2half_rn(t1[2]), __float2half_rn(t1[3]));
                }
                int rv = lane & 15, half = lane >> 4;
#pragma unroll
                for (int pp = 0; pp < 8; pp++) {
                    uint32_t bh[4];
                    int cV = pp * 16 + half * 8;
                    ldsm_x4_t(st + (rv * 136 + cV) * 2, bh);
#pragma unroll
                    for (int jj = 0; jj < 2; jj++)
                        mma_f16(o[2 * pp + jj], ah, bh[2 * jj], bh[2 * jj + 1]);
                }
            }
        }

        float inv0 = 1.f / l0, inv1 = 1.f / l1;
        int gr0 = i0 + lr0;
#pragma unroll
        for (int nt = 0; nt < 16; nt++) {
            int col = h * D_V + nt * 8 + ((lane & 3) << 1);
            *reinterpret_cast<uint32_t*>(&at[(long)gr0 * O_K + col]) =
                pack2(__float2half_rn(o[nt][0] * inv0), __float2half_rn(o[nt][1] * inv0));
            *reinterpret_cast<uint32_t*>(&at[(long)(gr0 + 8) * O_K + col]) =
                pack2(__float2half_rn(o[nt][2] * inv1), __float2half_rn(o[nt][3] * inv1));
        }
    }
}

// ---------------- hs converter (only remaining converter) ----------------
__global__ void cvt_single_kernel(const float* __restrict__ src,
                                  f16* __restrict__ h, long n)
{
    long i = ((long)blockIdx.x * blockDim.x + threadIdx.x) * 8;
    if (i >= n) return;
    float4 v0 = *reinterpret_cast<const float4*>(&src[i]);
    float4 v1 = *reinterpret_cast<const float4*>(&src[i + 4]);
    uint4 o;
    o.x = pack2(__float2half_rn(v0.x), __float2half_rn(v0.y));
    o.y = pack2(__float2half_rn(v0.z), __float2half_rn(v0.w));
    o.z = pack2(__float2half_rn(v1.x), __float2half_rn(v1.y));
    o.w = pack2(__float2half_rn(v1.z), __float2half_rn(v1.w));
    *reinterpret_cast<uint4*>(&h[i]) = o;
}

// ---------------- RMSNorm (single fp16 out) ----------------
__global__ void rmsnorm_kernel(const float* __restrict__ in,
                               const float* __restrict__ w,
                               f16* __restrict__ outh,
                               int L, int inStride, int outStride)
{
    int t = blockIdx.x;
    const float* x = in + (long)t * inStride;

    float ss = 0.f;
    for (int i = threadIdx.x; i < L; i += blockDim.x) {
        float v = x[i]; ss += v * v;
    }
    __shared__ float sh[33];
#pragma unroll
    for (int o = 16; o; o >>= 1) ss += __shfl_xor_sync(~0u, ss, o);
    int lane = threadIdx.x & 31, wrp = threadIdx.x >> 5;
    if (lane == 0) sh[wrp] = ss;
    __syncthreads();
    if (wrp == 0) {
        float v = (lane < (blockDim.x >> 5)) ? sh[lane] : 0.f;
#pragma unroll
        for (int o = 16; o; o >>= 1) v += __shfl_xor_sync(~0u, v, o);
        if (lane == 0) sh[32] = v;
    }
    __syncthreads();
    float r = rsqrtf(sh[32] / (float)L + EPS_RMS);
    for (int i = threadIdx.x; i < L; i += blockDim.x)
        outh[(long)t * outStride + i] = __float2half_rn(x[i] * r * w[i]);
}

// ---------------- k_pe rope + broadcast (reads combined qkv buffer) ----------------
__global__ void kpe_kernel(const int* __restrict__ positions,
                           const float* __restrict__ qkv,
                           f16* __restrict__ kf)
{
    long i = (long)blockIdx.x * blockDim.x + threadIdx.x;
    if (i >= (long)T_SEQ * (D_ROPE / 2)) return;
    int t = (int)(i >> 5), k = (int)(i & 31);
    float pos = (float)positions[t];
    float inv = expf(-logf(10000.0f) * (2.0f * k) / (float)D_ROPE);
    float ang = pos * inv;
    float cs = cosf(ang), sn = sinf(ang);
    float x1 = qkv[(long)t * QKV_N + Q_LORA + KV_LORA + 2 * k];
    float x2 = qkv[(long)t * QKV_N + Q_LORA + KV_LORA + 2 * k + 1];
    uint32_t pk = pack2(__float2half_rn(x1 * cs - x2 * sn),
                        __float2half_rn(x2 * cs + x1 * sn));
#pragma unroll
    for (int h = 0; h < NH; h++)
        *reinterpret_cast<uint32_t*>(&kf[((long)h * T_SEQ + t) * QK_HD + D_NOPE + 2 * k]) = pk;
}

// ---------------- Launch ----------------
extern "C" void kernel_launch(void* const* d_in, const int* in_sizes, int n_in,
                              void* d_out, int out_size)
{
    const int*   positions = (const int*)  d_in[0];
    const float* hs        = (const float*)d_in[1];
    const float* w_qa      = (const float*)d_in[2];
    const float* qa_ln_w   = (const float*)d_in[3];
    const float* w_qb      = (const float*)d_in[4];
    const float* w_kva     = (const float*)d_in[5];
    const float* kva_ln_w  = (const float*)d_in[6];
    const float* w_kvb     = (const float*)d_in[7];
    const float* w_o       = (const float*)d_in[8];
    float* out = (float*)d_out;

    float *p_qkv;
    f16 *phs, *qc, *kvc, *qf, *kf, *v, *at;

    cudaGetSymbolAddress((void**)&p_qkv,  g_qkv);
    cudaGetSymbolAddress((void**)&phs,    g_hs);
    cudaGetSymbolAddress((void**)&qc,     g_qc);
    cudaGetSymbolAddress((void**)&kvc,    g_kvc);
    cudaGetSymbolAddress((void**)&qf,     g_qf);
    cudaGetSymbolAddress((void**)&kf,     g_kf);
    cudaGetSymbolAddress((void**)&v,      g_v);
    cudaGetSymbolAddress((void**)&at,     g_at);

    cudaFuncSetAttribute(tgemm_nn<0,0>, cudaFuncAttributeMaxDynamicSharedMemorySize, G_SMEM);
    cudaFuncSetAttribute(tgemm_nn<0,1>, cudaFuncAttributeMaxDynamicSharedMemorySize, G_SMEM);
    cudaFuncSetAttribute(tgemm_nn<1,0>, cudaFuncAttributeMaxDynamicSharedMemorySize, G_SMEM);
    cudaFuncSetAttribute(tgemm_nn<2,0>, cudaFuncAttributeMaxDynamicSharedMemorySize, G_SMEM);
    cudaFuncSetAttribute(flash_kernel,  cudaFuncAttributeMaxDynamicSharedMemorySize, FA_SMEM);

    dim3 blk(256);
    auto cdiv = [](long a, long b) { return (int)((a + b - 1) / b); };

    // hs -> f16 (only converter left)
    cvt_single_kernel<<<cdiv((long)T_SEQ * HID / 8, 256), 256>>>(hs, phs, (long)T_SEQ * HID);

    // G1+G2 merged: qkv = hs @ [w_qa | w_kva] (fp32 B, fused convert)
    tgemm_nn<0,1><<<dim3(QKV_N/BN, T_SEQ/BM), blk, G_SMEM>>>(
        phs, w_qa, w_kva, p_qkv, nullptr, nullptr, nullptr,
        QKV_N, HID, HID, 0, QKV_N, 1.f);

    rmsnorm_kernel<<<T_SEQ, 256>>>(p_qkv,          qa_ln_w,  qc,  Q_LORA,  QKV_N, Q_LORA);
    rmsnorm_kernel<<<T_SEQ, 256>>>(p_qkv + Q_LORA, kva_ln_w, kvc, KV_LORA, QKV_N, KV_LORA);

    // k_pe rope + broadcast
    kpe_kernel<<<cdiv((long)T_SEQ * (D_ROPE/2), 256), 256>>>(positions, p_qkv, kf);

    // G3: q = qc @ w_qb (fp32 B) — fused RoPE epilogue
    tgemm_nn<1,0><<<dim3(QB_N/BN, T_SEQ/BM), blk, G_SMEM>>>(
        qc, w_qb, nullptr, nullptr, qf, nullptr, positions,
        QB_N, Q_LORA, Q_LORA, QB_N, 0, 1.f);

    // G4: kvup = kvc @ w_kvb (fp32 B) — fused scatter epilogue
    tgemm_nn<2,0><<<dim3(KVB_N/BN, T_SEQ/BM), blk, G_SMEM>>>(
        kvc, w_kvb, nullptr, nullptr, kf, v, nullptr,
        KVB_N, KV_LORA, KV_LORA, KVB_N, 0, 1.f);

    // Fused attention
    flash_kernel<<<dim3(NH, T_SEQ / 256), blk, FA_SMEM>>>(qf, kf, v, at);

    // G7: out = attn @ w_o (fp32 B)
    tgemm_nn<0,0><<<dim3(HID/BN, T_SEQ/BM), blk, G_SMEM>>>(
        at, w_o, nullptr, out, nullptr, nullptr, nullptr,
        HID, O_K, O_K, HID, HID, 1.f);
}

// round 15
// speedup vs baseline: 1.1305x; 1.1305x over previous
#include <cuda_runtime.h>
#include <cuda_fp16.h>
#include <math.h>
#include <stdint.h>

// ---------------- Problem constants ----------------
#define T_SEQ   2048
#define HID     5120
#define NH      16
#define D_NOPE  128
#define D_ROPE  64
#define D_V     128
#define Q_LORA  1536
#define KV_LORA 512
#define QK_HD   (D_NOPE + D_ROPE)   // 192
#define KVA_N   (KV_LORA + D_ROPE)  // 576
#define KVA_NP  640
#define QKV_N   (Q_LORA + KVA_NP)   // 2176 = 17 * 128
#define QB_N    (NH * QK_HD)        // 3072
#define KVB_N   (NH * (D_NOPE + D_V)) // 4096
#define O_K     (NH * D_V)          // 2048

static const float SCALE = 0.07216878364870322f; // 192^-0.5
#define EPS_RMS 1e-6f

typedef __half f16;

// ---------------- Scratch ----------------
__device__ float g_qkv  [T_SEQ * QKV_N];        // [qa(1536) | kv(576) | pad]

__device__ f16 g_hs    [T_SEQ * HID];
__device__ f16 g_wcomb [HID * QKV_N];           // [w_qa | w_kva | 0]
__device__ f16 g_wqb   [Q_LORA * QB_N];
__device__ f16 g_wkvb  [KV_LORA * KVB_N];
__device__ f16 g_wo    [O_K * HID];
__device__ f16 g_qc    [T_SEQ * Q_LORA];
__device__ f16 g_kvc   [T_SEQ * KV_LORA];
__device__ f16 g_qf    [(long)NH*T_SEQ*QK_HD];  // roped Q (G3 epilogue)
__device__ f16 g_kf    [(long)NH*T_SEQ*QK_HD];  // K (G4 epi + kpe)
__device__ f16 g_v     [(long)NH*T_SEQ*D_V];    // V (G4 epilogue)
__device__ f16 g_at    [T_SEQ * O_K];

// ---------------- helpers ----------------
__device__ __forceinline__ uint32_t smem_u32(const void* p) {
    return (uint32_t)__cvta_generic_to_shared(p);
}
__device__ __forceinline__ void cp16(uint32_t dst, const void* src) {
    asm volatile("cp.async.cg.shared.global [%0], [%1], 16;\n" :: "r"(dst), "l"(src));
}
__device__ __forceinline__ void cp_commit() {
    asm volatile("cp.async.commit_group;\n");
}
template<int NMAX>
__device__ __forceinline__ void cp_wait() {
    asm volatile("cp.async.wait_group %0;\n" :: "n"(NMAX));
}
__device__ __forceinline__ void ldsm_x4(uint32_t addr, uint32_t r[4]) {
    asm volatile("ldmatrix.sync.aligned.m8n8.x4.shared.b16 {%0,%1,%2,%3}, [%4];"
                 : "=r"(r[0]), "=r"(r[1]), "=r"(r[2]), "=r"(r[3]) : "r"(addr));
}
__device__ __forceinline__ void ldsm_x4_t(uint32_t addr, uint32_t r[4]) {
    asm volatile("ldmatrix.sync.aligned.m8n8.x4.trans.shared.b16 {%0,%1,%2,%3}, [%4];"
                 : "=r"(r[0]), "=r"(r[1]), "=r"(r[2]), "=r"(r[3]) : "r"(addr));
}
__device__ __forceinline__ void mma_f16(float c[4], const uint32_t a[4],
                                        uint32_t b0, uint32_t b1) {
    asm volatile(
        "mma.sync.aligned.m16n8k16.row.col.f32.f16.f16.f32 "
        "{%0,%1,%2,%3}, {%4,%5,%6,%7}, {%8,%9}, {%0,%1,%2,%3};"
        : "+f"(c[0]), "+f"(c[1]), "+f"(c[2]), "+f"(c[3])
        : "r"(a[0]), "r"(a[1]), "r"(a[2]), "r"(a[3]), "r"(b0), "r"(b1));
}
__device__ __forceinline__ uint32_t pack2(f16 a, f16 b) {
    __half2 t = __halves2half2(a, b);
    return *reinterpret_cast<uint32_t*>(&t);
}

// ---------------- NN tensor GEMM with fused epilogues ----------------
// EPI=0: C fp32.  EPI=1: roped Q -> qf f16.  EPI=2: scatter -> kf/v f16.
#define BM 128
#define BN 128
#define BK 16
#define G_STG  10496
#define G_SMEM (4 * G_STG)

template<int EPI>
__global__ __launch_bounds__(256, 2)
void tgemm_nn(const f16* __restrict__ A, const f16* __restrict__ B,
              float* __restrict__ C, f16* __restrict__ O1, f16* __restrict__ O2,
              const int* __restrict__ positions,
              int N, int K, int lda, int ldb, int ldc, float alpha)
{
    extern __shared__ char smem[];
    int row0 = blockIdx.y * BM;
    int col0 = blockIdx.x * BN;

    int tid  = threadIdx.x;
    int lane = tid & 31;
    int warp = tid >> 5;
    int wm   = warp >> 1;
    int wn   = warp & 1;

    int aRow = tid >> 1;
    int aKc  = (tid & 1) * 8;
    int bKr  = tid >> 4;
    int bNc  = (tid & 15) * 8;

    uint32_t sb = smem_u32(smem);

    auto issue = [&](int i) {
        int k0 = i * BK;
        uint32_t stg = sb + (i & 3) * G_STG;
        cp16(stg +        (aRow * 24 + aKc) * 2, &A[(long)(row0 + aRow) * lda + k0 + aKc]);
        cp16(stg + 6144 + (bKr * 136 + bNc) * 2, &B[(long)(k0 + bKr) * ldb + col0 + bNc]);
    };

    float acc[2][8][4];
#pragma unroll
    for (int i = 0; i < 2; i++)
#pragma unroll
        for (int j = 0; j < 8; j++)
#pragma unroll
            for (int q = 0; q < 4; q++) acc[i][j][q] = 0.f;

    int ntiles = K / BK;

    issue(0); cp_commit();
    if (ntiles > 1) issue(1);
    cp_commit();

    for (int i = 0; i < ntiles; i++) {
        if (i + 2 < ntiles) issue(i + 2);
        cp_commit();
        cp_wait<2>();
        __syncthreads();

        uint32_t stg = sb + (i & 3) * G_STG;
        uint32_t a_h[2][4];
#pragma unroll
        for (int mt = 0; mt < 2; mt++) {
            int r = wm * 32 + mt * 16 + (lane & 15);
            int c = (lane >> 4) * 8;
            ldsm_x4(stg + (r * 24 + c) * 2, a_h[mt]);
        }
        int rB    = lane & 15;
        int halfB = lane >> 4;
#pragma unroll
        for (int p = 0; p < 4; p++) {
            uint32_t bh[4];
            int c = wn * 64 + p * 16 + halfB * 8;
            ldsm_x4_t(stg + 6144 + (rB * 136 + c) * 2, bh);
#pragma unroll
            for (int mt = 0; mt < 2; mt++)
#pragma unroll
                for (int j = 0; j < 2; j++)
                    mma_f16(acc[mt][2 * p + j], a_h[mt], bh[2 * j], bh[2 * j + 1]);
        }
    }

    int gid = lane >> 2, tig = lane & 3;
#pragma unroll
    for (int mt = 0; mt < 2; mt++) {
        int rb = row0 + wm * 32 + mt * 16 + gid;
#pragma unroll
        for (int nt = 0; nt < 8; nt++) {
            int c = col0 + wn * 64 + nt * 8 + tig * 2;
            if (c >= N) continue;
            float p00 = acc[mt][nt][0], p01 = acc[mt][nt][1];
            float p10 = acc[mt][nt][2], p11 = acc[mt][nt][3];
            if (EPI == 0) {
                *reinterpret_cast<float2*>(&C[(long)rb * ldc + c]) =
                    make_float2(alpha * p00, alpha * p01);
                *reinterpret_cast<float2*>(&C[(long)(rb + 8) * ldc + c]) =
                    make_float2(alpha * p10, alpha * p11);
            } else if (EPI == 1) {
                int h = c / QK_HD, d = c % QK_HD;
#pragma unroll
                for (int rr = 0; rr < 2; rr++) {
                    int r = rb + rr * 8;
                    float v0 = rr ? p10 : p00, v1 = rr ? p11 : p01;
                    long dst = ((long)h * T_SEQ + r) * QK_HD + d;
                    if (d < D_NOPE) {
                        *reinterpret_cast<uint32_t*>(&O1[dst]) =
                            pack2(__float2half_rn(v0), __float2half_rn(v1));
                    } else {
                        int i2 = (d - D_NOPE) >> 1;
                        float pos = (float)positions[r];
                        float inv = expf(-logf(10000.0f) * (2.0f * i2) / (float)D_ROPE);
                        float ang = pos * inv;
                        float cs = cosf(ang), sn = sinf(ang);
                        *reinterpret_cast<uint32_t*>(&O1[dst]) =
                            pack2(__float2half_rn(v0 * cs - v1 * sn),
                                  __float2half_rn(v1 * cs + v0 * sn));
                    }
                }
            } else {
                int h = c >> 8, d = c & 255;
#pragma unroll
                for (int rr = 0; rr < 2; rr++) {
                    int r = rb + rr * 8;
                    float v0 = rr ? p10 : p00, v1 = rr ? p11 : p01;
                    uint32_t pk = pack2(__float2half_rn(v0), __float2half_rn(v1));
                    if (d < D_NOPE)
                        *reinterpret_cast<uint32_t*>(&O1[((long)h * T_SEQ + r) * QK_HD + d]) = pk;
                    else
                        *reinterpret_cast<uint32_t*>(&O2[((long)h * T_SEQ + r) * D_V + d - D_NOPE]) = pk;
                }
            }
        }
    }
}

// ---------------- Fused flash attention (all single-plane fp16) ----------------
#define FA_QSZ   (128 * 200 * 2)
#define FA_STG   6144
#define FA_SMEM  (FA_QSZ + 4 * FA_STG)

__global__ __launch_bounds__(256)
void flash_kernel(const f16* __restrict__ qf,
                  const f16* __restrict__ kf,  const f16* __restrict__ v,
                  f16* __restrict__ at)
{
    extern __shared__ char smem[];
    int h   = blockIdx.x;
    int tid = threadIdx.x;
    int lane = tid & 31;
    int wid  = tid >> 5;
    int wrow = wid * 16;

    uint32_t sQ  = smem_u32(smem);
    uint32_t stg = sQ + FA_QSZ;

    const long hT = (long)h * T_SEQ;

    auto loadQ = [&](int i0) {
#pragma unroll
        for (int it = 0; it < 12; it++) {
            int u = it * 256 + tid;
            int row = u / 24, off = (u % 24) * 8;
            cp16(sQ + (row * 200 + off) * 2, qf + (hT + i0 + row) * QK_HD + off);
        }
    };
    auto load_chunk = [&](int c) {
        uint32_t st = stg + (c & 3) * FA_STG;
        int j = c / 20, r = c % 20;
        if (r < 12) {
            int d0 = r * 16;
            int row = tid >> 1, off = (tid & 1) * 8;
            cp16(st + (row * 24 + off) * 2, kf + (hT + j * 128 + row) * QK_HD + d0 + off);
        } else {
            int q0 = (r - 12) * 16;
            int row = tid >> 4, off = (tid & 15) * 8;
            cp16(st + (row * 136 + off) * 2, v + (hT + j * 128 + q0 + row) * D_V + off);
        }
    };

    for (int rep = 0; rep < 2; rep++) {
        int iblk = rep == 0 ? blockIdx.y : (T_SEQ / 128 - 1) - blockIdx.y;
        int i0   = iblk * 128;
        int nch  = (iblk + 1) * 20;

        float s[16][4], o[16][4];
        float m0 = -1e30f, m1 = -1e30f, l0 = 0.f, l1 = 0.f;
#pragma unroll
        for (int nt = 0; nt < 16; nt++)
#pragma unroll
            for (int q = 0; q < 4; q++) o[nt][q] = 0.f;

        __syncthreads();
        loadQ(i0);
        load_chunk(0); cp_commit();
        load_chunk(1); cp_commit();

        int lr0 = wrow + (lane >> 2);
        int lr1 = lr0 + 8;

        for (int c = 0; c < nch; c++) {
            if (c + 2 < nch) load_chunk(c + 2);
            cp_commit();
            cp_wait<2>();
            __syncthreads();

            uint32_t st = stg + (c & 3) * FA_STG;
            int j = c / 20, r = c % 20;

            if (r < 12) {
                if (r == 0) {
#pragma unroll
                    for (int nt = 0; nt < 16; nt++)
#pragma unroll
                        for (int q = 0; q < 4; q++) s[nt][q] = 0.f;
                }
                uint32_t a_h[4];
                int ar = wrow + (lane & 15);
                int ac = r * 16 + (lane >> 4) * 8;
                ldsm_x4(sQ + (ar * 200 + ac) * 2, a_h);
                int g = lane >> 3, rr = lane & 7;
                int nbase = ((g >> 1) << 3) + rr;
                int cc = (g & 1) * 8;
#pragma unroll
                for (int p = 0; p < 8; p++) {
                    uint32_t bh[4];
                    ldsm_x4(st + ((p * 16 + nbase) * 24 + cc) * 2, bh);
#pragma unroll
                    for (int jj = 0; jj < 2; jj++)
                        mma_f16(s[2 * p + jj], a_h, bh[2 * jj], bh[2 * jj + 1]);
                }
                if (r == 11) {
#pragma unroll
                    for (int nt = 0; nt < 16; nt++)
#pragma unroll
                        for (int q = 0; q < 4; q++) s[nt][q] *= SCALE;
                    if (j == iblk) {
#pragma unroll
                        for (int nt = 0; nt < 16; nt++) {
                            int c0 = nt * 8 + ((lane & 3) << 1);
                            if (c0     > lr0) s[nt][0] = -1e30f;
                            if (c0 + 1 > lr0) s[nt][1] = -1e30f;
                            if (c0     > lr1) s[nt][2] = -1e30f;
                            if (c0 + 1 > lr1) s[nt][3] = -1e30f;
                        }
                    }
                    float mr0 = -1e30f, mr1 = -1e30f;
#pragma unroll
                    for (int nt = 0; nt < 16; nt++) {
                        mr0 = fmaxf(mr0, fmaxf(s[nt][0], s[nt][1]));
                        mr1 = fmaxf(mr1, fmaxf(s[nt][2], s[nt][3]));
                    }
                    mr0 = fmaxf(mr0, __shfl_xor_sync(~0u, mr0, 1));
                    mr0 = fmaxf(mr0, __shfl_xor_sync(~0u, mr0, 2));
                    mr1 = fmaxf(mr1, __shfl_xor_sync(~0u, mr1, 1));
                    mr1 = fmaxf(mr1, __shfl_xor_sync(~0u, mr1, 2));
                    float mn0 = fmaxf(m0, mr0), mn1 = fmaxf(m1, mr1);
                    float sc0 = __expf(m0 - mn0), sc1 = __expf(m1 - mn1);
                    float rs0 = 0.f, rs1 = 0.f;
#pragma unroll
                    for (int nt = 0; nt < 16; nt++) {
                        s[nt][0] = __expf(s[nt][0] - mn0); rs0 += s[nt][0];
                        s[nt][1] = __expf(s[nt][1] - mn0); rs0 += s[nt][1];
                        s[nt][2] = __expf(s[nt][2] - mn1); rs1 += s[nt][2];
                        s[nt][3] = __expf(s[nt][3] - mn1); rs1 += s[nt][3];
                    }
                    rs0 += __shfl_xor_sync(~0u, rs0, 1); rs0 += __shfl_xor_sync(~0u, rs0, 2);
                    rs1 += __shfl_xor_sync(~0u, rs1, 1); rs1 += __shfl_xor_sync(~0u, rs1, 2);
                    l0 = l0 * sc0 + rs0;  l1 = l1 * sc1 + rs1;
                    m0 = mn0; m1 = mn1;
#pragma unroll
                    for (int nt = 0; nt < 16; nt++) {
                        o[nt][0] *= sc0; o[nt][1] *= sc0;
                        o[nt][2] *= sc1; o[nt][3] *= sc1;
                    }
                }
            } else {
                int q = r - 12;
                uint32_t ah[4];
                {
                    const float* t0 = s[2 * q];
                    const float* t1 = s[2 * q + 1];
                    ah[0] = pack2(__float2half_rn(t0[0]), __float2half_rn(t0[1]));
                    ah[1] = pack2(__float2half_rn(t0[2]), __float2half_rn(t0[3]));
                    ah[2] = pack2(__float2half_rn(t1[0]), __float2half_rn(t1[1]));
                    ah[3] = pack2(__float2half_rn(t1[2]), __float2half_rn(t1[3]));
                }
                int rv = lane & 15, half = lane >> 4;
#pragma unroll
                for (int pp = 0; pp < 8; pp++) {
                    uint32_t bh[4];
                    int cV = pp * 16 + half * 8;
                    ldsm_x4_t(st + (rv * 136 + cV) * 2, bh);
#pragma unroll
                    for (int jj = 0; jj < 2; jj++)
                        mma_f16(o[2 * pp + jj], ah, bh[2 * jj], bh[2 * jj + 1]);
                }
            }
        }

        float inv0 = 1.f / l0, inv1 = 1.f / l1;
        int gr0 = i0 + lr0;
#pragma unroll
        for (int nt = 0; nt < 16; nt++) {
            int col = h * D_V + nt * 8 + ((lane & 3) << 1);
            *reinterpret_cast<uint32_t*>(&at[(long)gr0 * O_K + col]) =
                pack2(__float2half_rn(o[nt][0] * inv0), __float2half_rn(o[nt][1] * inv0));
            *reinterpret_cast<uint32_t*>(&at[(long)(gr0 + 8) * O_K + col]) =
                pack2(__float2half_rn(o[nt][2] * inv1), __float2half_rn(o[nt][3] * inv1));
        }
    }
}

// ---------------- converters ----------------
__global__ void cvt_single_kernel(const float* __restrict__ src,
                                  f16* __restrict__ h, long n)
{
    long i = ((long)blockIdx.x * blockDim.x + threadIdx.x) * 8;
    if (i >= n) return;
    float4 v0 = *reinterpret_cast<const float4*>(&src[i]);
    float4 v1 = *reinterpret_cast<const float4*>(&src[i + 4]);
    uint4 o;
    o.x = pack2(__float2half_rn(v0.x), __float2half_rn(v0.y));
    o.y = pack2(__float2half_rn(v0.z), __float2half_rn(v0.w));
    o.z = pack2(__float2half_rn(v1.x), __float2half_rn(v1.y));
    o.w = pack2(__float2half_rn(v1.z), __float2half_rn(v1.w));
    *reinterpret_cast<uint4*>(&h[i]) = o;
}
// combined weight: dst[r][c] = c<1536 ? w_qa[r][c] : (c-1536<576 ? w_kva[r][c-1536] : 0)
__global__ void cvt_comb_kernel(const float* __restrict__ wqa,
                                const float* __restrict__ wkva,
                                f16* __restrict__ dst)
{
    long i = (long)blockIdx.x * blockDim.x + threadIdx.x;
    if (i >= (long)HID * QKV_N) return;
    int r = (int)(i / QKV_N), c = (int)(i % QKV_N);
    float vv;
    if (c < Q_LORA)               vv = wqa[(long)r * Q_LORA + c];
    else if (c - Q_LORA < KVA_N)  vv = wkva[(long)r * KVA_N + (c - Q_LORA)];
    else                          vv = 0.f;
    dst[i] = __float2half_rn(vv);
}

// ---------------- RMSNorm (single fp16 out) ----------------
__global__ void rmsnorm_kernel(const float* __restrict__ in,
                               const float* __restrict__ w,
                               f16* __restrict__ outh,
                               int L, int inStride, int outStride)
{
    int t = blockIdx.x;
    const float* x = in + (long)t * inStride;

    float ss = 0.f;
    for (int i = threadIdx.x; i < L; i += blockDim.x) {
        float v = x[i]; ss += v * v;
    }
    __shared__ float sh[33];
#pragma unroll
    for (int o = 16; o; o >>= 1) ss += __shfl_xor_sync(~0u, ss, o);
    int lane = threadIdx.x & 31, wrp = threadIdx.x >> 5;
    if (lane == 0) sh[wrp] = ss;
    __syncthreads();
    if (wrp == 0) {
        float v = (lane < (blockDim.x >> 5)) ? sh[lane] : 0.f;
#pragma unroll
        for (int o = 16; o; o >>= 1) v += __shfl_xor_sync(~0u, v, o);
        if (lane == 0) sh[32] = v;
    }
    __syncthreads();
    float r = rsqrtf(sh[32] / (float)L + EPS_RMS);
    for (int i = threadIdx.x; i < L; i += blockDim.x)
        outh[(long)t * outStride + i] = __float2half_rn(x[i] * r * w[i]);
}

// ---------------- k_pe rope + broadcast (reads combined qkv buffer) ----------------
__global__ void kpe_kernel(const int* __restrict__ positions,
                           const float* __restrict__ qkv,
                           f16* __restrict__ kf)
{
    long i = (long)blockIdx.x * blockDim.x + threadIdx.x;
    if (i >= (long)T_SEQ * (D_ROPE / 2)) return;
    int t = (int)(i >> 5), k = (int)(i & 31);
    float pos = (float)positions[t];
    float inv = expf(-logf(10000.0f) * (2.0f * k) / (float)D_ROPE);
    float ang = pos * inv;
    float cs = cosf(ang), sn = sinf(ang);
    float x1 = qkv[(long)t * QKV_N + Q_LORA + KV_LORA + 2 * k];
    float x2 = qkv[(long)t * QKV_N + Q_LORA + KV_LORA + 2 * k + 1];
    uint32_t pk = pack2(__float2half_rn(x1 * cs - x2 * sn),
                        __float2half_rn(x2 * cs + x1 * sn));
#pragma unroll
    for (int h = 0; h < NH; h++)
        *reinterpret_cast<uint32_t*>(&kf[((long)h * T_SEQ + t) * QK_HD + D_NOPE + 2 * k]) = pk;
}

// ---------------- Launch ----------------
extern "C" void kernel_launch(void* const* d_in, const int* in_sizes, int n_in,
                              void* d_out, int out_size)
{
    const int*   positions = (const int*)  d_in[0];
    const float* hs        = (const float*)d_in[1];
    const float* w_qa      = (const float*)d_in[2];
    const float* qa_ln_w   = (const float*)d_in[3];
    const float* w_qb      = (const float*)d_in[4];
    const float* w_kva     = (const float*)d_in[5];
    const float* kva_ln_w  = (const float*)d_in[6];
    const float* w_kvb     = (const float*)d_in[7];
    const float* w_o       = (const float*)d_in[8];
    float* out = (float*)d_out;

    float *p_qkv;
    f16 *phs, *wcomb, *wqb, *wkvb, *wo;
    f16 *qc, *kvc, *qf, *kf, *v, *at;

    cudaGetSymbolAddress((void**)&p_qkv,  g_qkv);
    cudaGetSymbolAddress((void**)&phs,    g_hs);
    cudaGetSymbolAddress((void**)&wcomb,  g_wcomb);
    cudaGetSymbolAddress((void**)&wqb,    g_wqb);
    cudaGetSymbolAddress((void**)&wkvb,   g_wkvb);
    cudaGetSymbolAddress((void**)&wo,     g_wo);
    cudaGetSymbolAddress((void**)&qc,     g_qc);
    cudaGetSymbolAddress((void**)&kvc,    g_kvc);
    cudaGetSymbolAddress((void**)&qf,     g_qf);
    cudaGetSymbolAddress((void**)&kf,     g_kf);
    cudaGetSymbolAddress((void**)&v,      g_v);
    cudaGetSymbolAddress((void**)&at,     g_at);

    cudaFuncSetAttribute(tgemm_nn<0>,  cudaFuncAttributeMaxDynamicSharedMemorySize, G_SMEM);
    cudaFuncSetAttribute(tgemm_nn<1>,  cudaFuncAttributeMaxDynamicSharedMemorySize, G_SMEM);
    cudaFuncSetAttribute(tgemm_nn<2>,  cudaFuncAttributeMaxDynamicSharedMemorySize, G_SMEM);
    cudaFuncSetAttribute(flash_kernel, cudaFuncAttributeMaxDynamicSharedMemorySize, FA_SMEM);

    dim3 blk(256);
    auto cdiv = [](long a, long b) { return (int)((a + b - 1) / b); };

    // converters
    cvt_single_kernel<<<cdiv((long)T_SEQ * HID / 8, 256), 256>>>(hs, phs, (long)T_SEQ * HID);
    cvt_comb_kernel<<<cdiv((long)HID * QKV_N, 256), 256>>>(w_qa, w_kva, wcomb);
    cvt_single_kernel<<<cdiv((long)Q_LORA * QB_N / 8, 256), 256>>>(w_qb, wqb, (long)Q_LORA * QB_N);
    cvt_single_kernel<<<cdiv((long)KV_LORA * KVB_N / 8, 256), 256>>>(w_kvb, wkvb, (long)KV_LORA * KVB_N);
    cvt_single_kernel<<<cdiv((long)O_K * HID / 8, 256), 256>>>(w_o, wo, (long)O_K * HID);

    // G1+G2 merged: qkv = hs @ [w_qa | w_kva] (N=2176, K=5120)
    tgemm_nn<0><<<dim3(QKV_N/BN, T_SEQ/BM), blk, G_SMEM>>>(
        phs, wcomb, p_qkv, nullptr, nullptr, nullptr,
        QKV_N, HID, HID, QKV_N, QKV_N, 1.f);

    rmsnorm_kernel<<<T_SEQ, 256>>>(p_qkv,          qa_ln_w,  qc,  Q_LORA,  QKV_N, Q_LORA);
    rmsnorm_kernel<<<T_SEQ, 256>>>(p_qkv + Q_LORA, kva_ln_w, kvc, KV_LORA, QKV_N, KV_LORA);

    // k_pe rope + broadcast
    kpe_kernel<<<cdiv((long)T_SEQ * (D_ROPE/2), 256), 256>>>(positions, p_qkv, kf);

    // G3: q = qc @ w_qb — fused RoPE epilogue
    tgemm_nn<1><<<dim3(QB_N/BN, T_SEQ/BM), blk, G_SMEM>>>(
        qc, wqb, nullptr, qf, nullptr, positions,
        QB_N, Q_LORA, Q_LORA, QB_N, 0, 1.f);

    // G4: kvup = kvc @ w_kvb — fused scatter epilogue
    tgemm_nn<2><<<dim3(KVB_N/BN, T_SEQ/BM), blk, G_SMEM>>>(
        kvc, wkvb, nullptr, kf, v, nullptr,
        KVB_N, KV_LORA, KV_LORA, KVB_N, 0, 1.f);

    // Fused attention
    flash_kernel<<<dim3(NH, T_SEQ / 256), blk, FA_SMEM>>>(qf, kf, v, at);

    // G7: out = attn @ w_o
    tgemm_nn<0><<<dim3(HID/BN, T_SEQ/BM), blk, G_SMEM>>>(
        at, wo, out, nullptr, nullptr, nullptr,
        HID, O_K, O_K, HID, HID, 1.f);
}

// round 16
// speedup vs baseline: 1.1319x; 1.0012x over previous
#include <cuda_runtime.h>
#include <cuda_fp16.h>
#include <math.h>
#include <stdint.h>

// ---------------- Problem constants ----------------
#define T_SEQ   2048
#define HID     5120
#define NH      16
#define D_NOPE  128
#define D_ROPE  64
#define D_V     128
#define Q_LORA  1536
#define KV_LORA 512
#define QK_HD   (D_NOPE + D_ROPE)   // 192
#define KVA_N   (KV_LORA + D_ROPE)  // 576
#define KVA_NP  640
#define QKV_N   (Q_LORA + KVA_NP)   // 2176 = 17 * 128
#define QB_N    (NH * QK_HD)        // 3072
#define KVB_N   (NH * (D_NOPE + D_V)) // 4096
#define O_K     (NH * D_V)          // 2048

static const float SCALE = 0.07216878364870322f; // 192^-0.5
#define EPS_RMS 1e-6f
#define NSM_X2  296                 // 148 SMs x 2 CTAs

typedef __half f16;

// ---------------- Scratch ----------------
__device__ float g_qkv  [T_SEQ * QKV_N];

__device__ f16 g_hs    [T_SEQ * HID];
__device__ f16 g_wcomb [HID * QKV_N];
__device__ f16 g_wqb   [Q_LORA * QB_N];
__device__ f16 g_wkvb  [KV_LORA * KVB_N];
__device__ f16 g_wo    [O_K * HID];
__device__ f16 g_qc    [T_SEQ * Q_LORA];
__device__ f16 g_kvc   [T_SEQ * KV_LORA];
__device__ f16 g_qf    [(long)NH*T_SEQ*QK_HD];
__device__ f16 g_kf    [(long)NH*T_SEQ*QK_HD];
__device__ f16 g_v     [(long)NH*T_SEQ*D_V];
__device__ f16 g_at    [T_SEQ * O_K];

// ---------------- helpers ----------------
__device__ __forceinline__ uint32_t smem_u32(const void* p) {
    return (uint32_t)__cvta_generic_to_shared(p);
}
__device__ __forceinline__ void cp16(uint32_t dst, const void* src) {
    asm volatile("cp.async.cg.shared.global [%0], [%1], 16;\n" :: "r"(dst), "l"(src));
}
__device__ __forceinline__ void cp_commit() {
    asm volatile("cp.async.commit_group;\n");
}
template<int NMAX>
__device__ __forceinline__ void cp_wait() {
    asm volatile("cp.async.wait_group %0;\n" :: "n"(NMAX));
}
__device__ __forceinline__ void ldsm_x4(uint32_t addr, uint32_t r[4]) {
    asm volatile("ldmatrix.sync.aligned.m8n8.x4.shared.b16 {%0,%1,%2,%3}, [%4];"
                 : "=r"(r[0]), "=r"(r[1]), "=r"(r[2]), "=r"(r[3]) : "r"(addr));
}
__device__ __forceinline__ void ldsm_x4_t(uint32_t addr, uint32_t r[4]) {
    asm volatile("ldmatrix.sync.aligned.m8n8.x4.trans.shared.b16 {%0,%1,%2,%3}, [%4];"
                 : "=r"(r[0]), "=r"(r[1]), "=r"(r[2]), "=r"(r[3]) : "r"(addr));
}
__device__ __forceinline__ void mma_f16(float c[4], const uint32_t a[4],
                                        uint32_t b0, uint32_t b1) {
    asm volatile(
        "mma.sync.aligned.m16n8k16.row.col.f32.f16.f16.f32 "
        "{%0,%1,%2,%3}, {%4,%5,%6,%7}, {%8,%9}, {%0,%1,%2,%3};"
        : "+f"(c[0]), "+f"(c[1]), "+f"(c[2]), "+f"(c[3])
        : "r"(a[0]), "r"(a[1]), "r"(a[2]), "r"(a[3]), "r"(b0), "r"(b1));
}
__device__ __forceinline__ uint32_t pack2(f16 a, f16 b) {
    __half2 t = __halves2half2(a, b);
    return *reinterpret_cast<uint32_t*>(&t);
}

// ---------------- Persistent-tile NN tensor GEMM with fused epilogues ----------
// EPI=0: C fp32.  EPI=1: roped Q -> qf f16.  EPI=2: scatter -> kf/v f16.
// Grid = NSM_X2 CTAs; each loops over output tiles (no wave quantization).
#define BM 128
#define BN 128
#define BK 16
#define G_STG  10496
#define G_SMEM (4 * G_STG)

template<int EPI>
__global__ __launch_bounds__(256, 2)
void tgemm_nn(const f16* __restrict__ A, const f16* __restrict__ B,
              float* __restrict__ C, f16* __restrict__ O1, f16* __restrict__ O2,
              const int* __restrict__ positions,
              int tiles_n, int N, int K, int lda, int ldb, int ldc, float alpha)
{
    extern __shared__ char smem[];
    int tid  = threadIdx.x;
    int lane = tid & 31;
    int warp = tid >> 5;
    int wm   = warp >> 1;
    int wn   = warp & 1;

    int aRow = tid >> 1;
    int aKc  = (tid & 1) * 8;
    int bKr  = tid >> 4;
    int bNc  = (tid & 15) * 8;

    uint32_t sb = smem_u32(smem);
    int ntiles     = K / BK;
    int tilesTotal = tiles_n * (T_SEQ / BM);

    for (int t = blockIdx.x; t < tilesTotal; t += gridDim.x) {
        int row0 = (t / tiles_n) * BM;
        int col0 = (t % tiles_n) * BN;

        auto issue = [&](int i) {
            int k0 = i * BK;
            uint32_t stg = sb + (i & 3) * G_STG;
            cp16(stg +        (aRow * 24 + aKc) * 2, &A[(long)(row0 + aRow) * lda + k0 + aKc]);
            cp16(stg + 6144 + (bKr * 136 + bNc) * 2, &B[(long)(k0 + bKr) * ldb + col0 + bNc]);
        };

        float acc[2][8][4];
#pragma unroll
        for (int i = 0; i < 2; i++)
#pragma unroll
            for (int j = 0; j < 8; j++)
#pragma unroll
                for (int q = 0; q < 4; q++) acc[i][j][q] = 0.f;

        issue(0); cp_commit();
        if (ntiles > 1) issue(1);
        cp_commit();

        for (int i = 0; i < ntiles; i++) {
            if (i + 2 < ntiles) issue(i + 2);
            cp_commit();
            cp_wait<2>();
            __syncthreads();

            uint32_t stg = sb + (i & 3) * G_STG;
            uint32_t a_h[2][4];
#pragma unroll
            for (int mt = 0; mt < 2; mt++) {
                int r = wm * 32 + mt * 16 + (lane & 15);
                int c = (lane >> 4) * 8;
                ldsm_x4(stg + (r * 24 + c) * 2, a_h[mt]);
            }
            int rB    = lane & 15;
            int halfB = lane >> 4;
#pragma unroll
            for (int p = 0; p < 4; p++) {
                uint32_t bh[4];
                int c = wn * 64 + p * 16 + halfB * 8;
                ldsm_x4_t(stg + 6144 + (rB * 136 + c) * 2, bh);
#pragma unroll
                for (int mt = 0; mt < 2; mt++)
#pragma unroll
                    for (int j = 0; j < 2; j++)
                        mma_f16(acc[mt][2 * p + j], a_h[mt], bh[2 * j], bh[2 * j + 1]);
            }
        }
        cp_wait<0>();
        __syncthreads();   // smem safe for next tile's prologue

        int gid = lane >> 2, tig = lane & 3;
#pragma unroll
        for (int mt = 0; mt < 2; mt++) {
            int rb = row0 + wm * 32 + mt * 16 + gid;
#pragma unroll
            for (int nt = 0; nt < 8; nt++) {
                int c = col0 + wn * 64 + nt * 8 + tig * 2;
                if (c >= N) continue;
                float p00 = acc[mt][nt][0], p01 = acc[mt][nt][1];
                float p10 = acc[mt][nt][2], p11 = acc[mt][nt][3];
                if (EPI == 0) {
                    *reinterpret_cast<float2*>(&C[(long)rb * ldc + c]) =
                        make_float2(alpha * p00, alpha * p01);
                    *reinterpret_cast<float2*>(&C[(long)(rb + 8) * ldc + c]) =
                        make_float2(alpha * p10, alpha * p11);
                } else if (EPI == 1) {
                    int h = c / QK_HD, d = c % QK_HD;
#pragma unroll
                    for (int rr = 0; rr < 2; rr++) {
                        int r = rb + rr * 8;
                        float v0 = rr ? p10 : p00, v1 = rr ? p11 : p01;
                        long dst = ((long)h * T_SEQ + r) * QK_HD + d;
                        if (d < D_NOPE) {
                            *reinterpret_cast<uint32_t*>(&O1[dst]) =
                                pack2(__float2half_rn(v0), __float2half_rn(v1));
                        } else {
                            int i2 = (d - D_NOPE) >> 1;
                            float pos = (float)positions[r];
                            float inv = expf(-logf(10000.0f) * (2.0f * i2) / (float)D_ROPE);
                            float ang = pos * inv;
                            float cs = cosf(ang), sn = sinf(ang);
                            *reinterpret_cast<uint32_t*>(&O1[dst]) =
                                pack2(__float2half_rn(v0 * cs - v1 * sn),
                                      __float2half_rn(v1 * cs + v0 * sn));
                        }
                    }
                } else {
                    int h = c >> 8, d = c & 255;
#pragma unroll
                    for (int rr = 0; rr < 2; rr++) {
                        int r = rb + rr * 8;
                        float v0 = rr ? p10 : p00, v1 = rr ? p11 : p01;
                        uint32_t pk = pack2(__float2half_rn(v0), __float2half_rn(v1));
                        if (d < D_NOPE)
                            *reinterpret_cast<uint32_t*>(&O1[((long)h * T_SEQ + r) * QK_HD + d]) = pk;
                        else
                            *reinterpret_cast<uint32_t*>(&O2[((long)h * T_SEQ + r) * D_V + d - D_NOPE]) = pk;
                    }
                }
            }
        }
    }
}

// ---------------- Fused flash attention (all single-plane fp16) ----------------
#define FA_QSZ   (128 * 200 * 2)
#define FA_STG   6144
#define FA_SMEM  (FA_QSZ + 4 * FA_STG)

__global__ __launch_bounds__(256)
void flash_kernel(const f16* __restrict__ qf,
                  const f16* __restrict__ kf,  const f16* __restrict__ v,
                  f16* __restrict__ at)
{
    extern __shared__ char smem[];
    int h   = blockIdx.x;
    int tid = threadIdx.x;
    int lane = tid & 31;
    int wid  = tid >> 5;
    int wrow = wid * 16;

    uint32_t sQ  = smem_u32(smem);
    uint32_t stg = sQ + FA_QSZ;

    const long hT = (long)h * T_SEQ;

    auto loadQ = [&](int i0) {
#pragma unroll
        for (int it = 0; it < 12; it++) {
            int u = it * 256 + tid;
            int row = u / 24, off = (u % 24) * 8;
            cp16(sQ + (row * 200 + off) * 2, qf + (hT + i0 + row) * QK_HD + off);
        }
    };
    auto load_chunk = [&](int c) {
        uint32_t st = stg + (c & 3) * FA_STG;
        int j = c / 20, r = c % 20;
        if (r < 12) {
            int d0 = r * 16;
            int row = tid >> 1, off = (tid & 1) * 8;
            cp16(st + (row * 24 + off) * 2, kf + (hT + j * 128 + row) * QK_HD + d0 + off);
        } else {
            int q0 = (r - 12) * 16;
            int row = tid >> 4, off = (tid & 15) * 8;
            cp16(st + (row * 136 + off) * 2, v + (hT + j * 128 + q0 + row) * D_V + off);
        }
    };

    for (int rep = 0; rep < 2; rep++) {
        int iblk = rep == 0 ? blockIdx.y : (T_SEQ / 128 - 1) - blockIdx.y;
        int i0   = iblk * 128;
        int nch  = (iblk + 1) * 20;

        float s[16][4], o[16][4];
        float m0 = -1e30f, m1 = -1e30f, l0 = 0.f, l1 = 0.f;
#pragma unroll
        for (int nt = 0; nt < 16; nt++)
#pragma unroll
            for (int q = 0; q < 4; q++) o[nt][q] = 0.f;

        __syncthreads();
        loadQ(i0);
        load_chunk(0); cp_commit();
        load_chunk(1); cp_commit();

        int lr0 = wrow + (lane >> 2);
        int lr1 = lr0 + 8;

        for (int c = 0; c < nch; c++) {
            if (c + 2 < nch) load_chunk(c + 2);
            cp_commit();
            cp_wait<2>();
            __syncthreads();

            uint32_t st = stg + (c & 3) * FA_STG;
            int j = c / 20, r = c % 20;

            if (r < 12) {
                if (r == 0) {
#pragma unroll
                    for (int nt = 0; nt < 16; nt++)
#pragma unroll
                        for (int q = 0; q < 4; q++) s[nt][q] = 0.f;
                }
                uint32_t a_h[4];
                int ar = wrow + (lane & 15);
                int ac = r * 16 + (lane >> 4) * 8;
                ldsm_x4(sQ + (ar * 200 + ac) * 2, a_h);
                int g = lane >> 3, rr = lane & 7;
                int nbase = ((g >> 1) << 3) + rr;
                int cc = (g & 1) * 8;
#pragma unroll
                for (int p = 0; p < 8; p++) {
                    uint32_t bh[4];
                    ldsm_x4(st + ((p * 16 + nbase) * 24 + cc) * 2, bh);
#pragma unroll
                    for (int jj = 0; jj < 2; jj++)
                        mma_f16(s[2 * p + jj], a_h, bh[2 * jj], bh[2 * jj + 1]);
                }
                if (r == 11) {
#pragma unroll
                    for (int nt = 0; nt < 16; nt++)
#pragma unroll
                        for (int q = 0; q < 4; q++) s[nt][q] *= SCALE;
                    if (j == iblk) {
#pragma unroll
                        for (int nt = 0; nt < 16; nt++) {
                            int c0 = nt * 8 + ((lane & 3) << 1);
                            if (c0     > lr0) s[nt][0] = -1e30f;
                            if (c0 + 1 > lr0) s[nt][1] = -1e30f;
                            if (c0     > lr1) s[nt][2] = -1e30f;
                            if (c0 + 1 > lr1) s[nt][3] = -1e30f;
                        }
                    }
                    float mr0 = -1e30f, mr1 = -1e30f;
#pragma unroll
                    for (int nt = 0; nt < 16; nt++) {
                        mr0 = fmaxf(mr0, fmaxf(s[nt][0], s[nt][1]));
                        mr1 = fmaxf(mr1, fmaxf(s[nt][2], s[nt][3]));
                    }
                    mr0 = fmaxf(mr0, __shfl_xor_sync(~0u, mr0, 1));
                    mr0 = fmaxf(mr0, __shfl_xor_sync(~0u, mr0, 2));
                    mr1 = fmaxf(mr1, __shfl_xor_sync(~0u, mr1, 1));
                    mr1 = fmaxf(mr1, __shfl_xor_sync(~0u, mr1, 2));
                    float mn0 = fmaxf(m0, mr0), mn1 = fmaxf(m1, mr1);
                    float sc0 = __expf(m0 - mn0), sc1 = __expf(m1 - mn1);
                    float rs0 = 0.f, rs1 = 0.f;
#pragma unroll
                    for (int nt = 0; nt < 16; nt++) {
                        s[nt][0] = __expf(s[nt][0] - mn0); rs0 += s[nt][0];
                        s[nt][1] = __expf(s[nt][1] - mn0); rs0 += s[nt][1];
                        s[nt][2] = __expf(s[nt][2] - mn1); rs1 += s[nt][2];
                        s[nt][3] = __expf(s[nt][3] - mn1); rs1 += s[nt][3];
                    }
                    rs0 += __shfl_xor_sync(~0u, rs0, 1); rs0 += __shfl_xor_sync(~0u, rs0, 2);
                    rs1 += __shfl_xor_sync(~0u, rs1, 1); rs1 += __shfl_xor_sync(~0u, rs1, 2);
                    l0 = l0 * sc0 + rs0;  l1 = l1 * sc1 + rs1;
                    m0 = mn0; m1 = mn1;
#pragma unroll
                    for (int nt = 0; nt < 16; nt++) {
                        o[nt][0] *= sc0; o[nt][1] *= sc0;
                        o[nt][2] *= sc1; o[nt][3] *= sc1;
                    }
                }
            } else {
                int q = r - 12;
                uint32_t ah[4];
                {
                    const float* t0 = s[2 * q];
                    const float* t1 = s[2 * q + 1];
                    ah[0] = pack2(__float2half_rn(t0[0]), __float2half_rn(t0[1]));
                    ah[1] = pack2(__float2half_rn(t0[2]), __float2half_rn(t0[3]));
                    ah[2] = pack2(__float2half_rn(t1[0]), __float2half_rn(t1[1]));
                    ah[3] = pack2(__float2half_rn(t1[2]), __float2half_rn(t1[3]));
                }
                int rv = lane & 15, half = lane >> 4;
#pragma unroll
                for (int pp = 0; pp < 8; pp++) {
                    uint32_t bh[4];
                    int cV = pp * 16 + half * 8;
                    ldsm_x4_t(st + (rv * 136 + cV) * 2, bh);
#pragma unroll
                    for (int jj = 0; jj < 2; jj++)
                        mma_f16(o[2 * pp + jj], ah, bh[2 * jj], bh[2 * jj + 1]);
                }
            }
        }

        float inv0 = 1.f / l0, inv1 = 1.f / l1;
        int gr0 = i0 + lr0;
#pragma unroll
        for (int nt = 0; nt < 16; nt++) {
            int col = h * D_V + nt * 8 + ((lane & 3) << 1);
            *reinterpret_cast<uint32_t*>(&at[(long)gr0 * O_K + col]) =
                pack2(__float2half_rn(o[nt][0] * inv0), __float2half_rn(o[nt][1] * inv0));
            *reinterpret_cast<uint32_t*>(&at[(long)(gr0 + 8) * O_K + col]) =
                pack2(__float2half_rn(o[nt][2] * inv1), __float2half_rn(o[nt][3] * inv1));
        }
    }
}

// ---------------- merged flat converter (hs, wqb, wkvb, wo in one launch) ----------
#define CVT_S0 ((long)T_SEQ * HID)
#define CVT_S1 ((long)Q_LORA * QB_N)
#define CVT_S2 ((long)KV_LORA * KVB_N)
#define CVT_S3 ((long)O_K * HID)
#define CVT_TOTAL (CVT_S0 + CVT_S1 + CVT_S2 + CVT_S3)

__global__ void cvt_all_kernel(const float* __restrict__ s0, f16* __restrict__ d0,
                               const float* __restrict__ s1, f16* __restrict__ d1,
                               const float* __restrict__ s2, f16* __restrict__ d2,
                               const float* __restrict__ s3, f16* __restrict__ d3)
{
    long i = ((long)blockIdx.x * blockDim.x + threadIdx.x) * 8;
    if (i >= CVT_TOTAL) return;
    const float* src; f16* dst; long off = i;
    if (off < CVT_S0)      { src = s0; dst = d0; }
    else if ((off -= CVT_S0) < CVT_S1) { src = s1; dst = d1; }
    else if ((off -= CVT_S1) < CVT_S2) { src = s2; dst = d2; }
    else { off -= CVT_S2; src = s3; dst = d3; }
    float4 v0 = *reinterpret_cast<const float4*>(&src[off]);
    float4 v1 = *reinterpret_cast<const float4*>(&src[off + 4]);
    uint4 o;
    o.x = pack2(__float2half_rn(v0.x), __float2half_rn(v0.y));
    o.y = pack2(__float2half_rn(v0.z), __float2half_rn(v0.w));
    o.z = pack2(__float2half_rn(v1.x), __float2half_rn(v1.y));
    o.w = pack2(__float2half_rn(v1.z), __float2half_rn(v1.w));
    *reinterpret_cast<uint4*>(&dst[off]) = o;
}
// combined G1G2 weight
__global__ void cvt_comb_kernel(const float* __restrict__ wqa,
                                const float* __restrict__ wkva,
                                f16* __restrict__ dst)
{
    long i = (long)blockIdx.x * blockDim.x + threadIdx.x;
    if (i >= (long)HID * QKV_N) return;
    int r = (int)(i / QKV_N), c = (int)(i % QKV_N);
    float vv;
    if (c < Q_LORA)               vv = wqa[(long)r * Q_LORA + c];
    else if (c - Q_LORA < KVA_N)  vv = wkva[(long)r * KVA_N + (c - Q_LORA)];
    else                          vv = 0.f;
    dst[i] = __float2half_rn(vv);
}

// ---------------- RMSNorm (single fp16 out) ----------------
__global__ void rmsnorm_kernel(const float* __restrict__ in,
                               const float* __restrict__ w,
                               f16* __restrict__ outh,
                               int L, int inStride, int outStride)
{
    int t = blockIdx.x;
    const float* x = in + (long)t * inStride;

    float ss = 0.f;
    for (int i = threadIdx.x; i < L; i += blockDim.x) {
        float v = x[i]; ss += v * v;
    }
    __shared__ float sh[33];
#pragma unroll
    for (int o = 16; o; o >>= 1) ss += __shfl_xor_sync(~0u, ss, o);
    int lane = threadIdx.x & 31, wrp = threadIdx.x >> 5;
    if (lane == 0) sh[wrp] = ss;
    __syncthreads();
    if (wrp == 0) {
        float v = (lane < (blockDim.x >> 5)) ? sh[lane] : 0.f;
#pragma unroll
        for (int o = 16; o; o >>= 1) v += __shfl_xor_sync(~0u, v, o);
        if (lane == 0) sh[32] = v;
    }
    __syncthreads();
    float r = rsqrtf(sh[32] / (float)L + EPS_RMS);
    for (int i = threadIdx.x; i < L; i += blockDim.x)
        outh[(long)t * outStride + i] = __float2half_rn(x[i] * r * w[i]);
}

// ---------------- k_pe rope + broadcast ----------------
__global__ void kpe_kernel(const int* __restrict__ positions,
                           const float* __restrict__ qkv,
                           f16* __restrict__ kf)
{
    long i = (long)blockIdx.x * blockDim.x + threadIdx.x;
    if (i >= (long)T_SEQ * (D_ROPE / 2)) return;
    int t = (int)(i >> 5), k = (int)(i & 31);
    float pos = (float)positions[t];
    float inv = expf(-logf(10000.0f) * (2.0f * k) / (float)D_ROPE);
    float ang = pos * inv;
    float cs = cosf(ang), sn = sinf(ang);
    float x1 = qkv[(long)t * QKV_N + Q_LORA + KV_LORA + 2 * k];
    float x2 = qkv[(long)t * QKV_N + Q_LORA + KV_LORA + 2 * k + 1];
    uint32_t pk = pack2(__float2half_rn(x1 * cs - x2 * sn),
                        __float2half_rn(x2 * cs + x1 * sn));
#pragma unroll
    for (int h = 0; h < NH; h++)
        *reinterpret_cast<uint32_t*>(&kf[((long)h * T_SEQ + t) * QK_HD + D_NOPE + 2 * k]) = pk;
}

// ---------------- Launch ----------------
extern "C" void kernel_launch(void* const* d_in, const int* in_sizes, int n_in,
                              void* d_out, int out_size)
{
    const int*   positions = (const int*)  d_in[0];
    const float* hs        = (const float*)d_in[1];
    const float* w_qa      = (const float*)d_in[2];
    const float* qa_ln_w   = (const float*)d_in[3];
    const float* w_qb      = (const float*)d_in[4];
    const float* w_kva     = (const float*)d_in[5];
    const float* kva_ln_w  = (const float*)d_in[6];
    const float* w_kvb     = (const float*)d_in[7];
    const float* w_o       = (const float*)d_in[8];
    float* out = (float*)d_out;

    float *p_qkv;
    f16 *phs, *wcomb, *wqb, *wkvb, *wo;
    f16 *qc, *kvc, *qf, *kf, *v, *at;

    cudaGetSymbolAddress((void**)&p_qkv,  g_qkv);
    cudaGetSymbolAddress((void**)&phs,    g_hs);
    cudaGetSymbolAddress((void**)&wcomb,  g_wcomb);
    cudaGetSymbolAddress((void**)&wqb,    g_wqb);
    cudaGetSymbolAddress((void**)&wkvb,   g_wkvb);
    cudaGetSymbolAddress((void**)&wo,     g_wo);
    cudaGetSymbolAddress((void**)&qc,     g_qc);
    cudaGetSymbolAddress((void**)&kvc,    g_kvc);
    cudaGetSymbolAddress((void**)&qf,     g_qf);
    cudaGetSymbolAddress((void**)&kf,     g_kf);
    cudaGetSymbolAddress((void**)&v,      g_v);
    cudaGetSymbolAddress((void**)&at,     g_at);

    cudaFuncSetAttribute(tgemm_nn<0>,  cudaFuncAttributeMaxDynamicSharedMemorySize, G_SMEM);
    cudaFuncSetAttribute(tgemm_nn<1>,  cudaFuncAttributeMaxDynamicSharedMemorySize, G_SMEM);
    cudaFuncSetAttribute(tgemm_nn<2>,  cudaFuncAttributeMaxDynamicSharedMemorySize, G_SMEM);
    cudaFuncSetAttribute(flash_kernel, cudaFuncAttributeMaxDynamicSharedMemorySize, FA_SMEM);

    dim3 blk(256);
    auto cdiv = [](long a, long b) { return (int)((a + b - 1) / b); };

    // converters (2 launches)
    cvt_all_kernel<<<cdiv(CVT_TOTAL / 8, 256), 256>>>(hs, phs, w_qb, wqb, w_kvb, wkvb, w_o, wo);
    cvt_comb_kernel<<<cdiv((long)HID * QKV_N, 256), 256>>>(w_qa, w_kva, wcomb);

    // G1+G2 merged: qkv = hs @ [w_qa | w_kva]  (272 tiles)
    tgemm_nn<0><<<NSM_X2, blk, G_SMEM>>>(
        phs, wcomb, p_qkv, nullptr, nullptr, nullptr,
        QKV_N / BN, QKV_N, HID, HID, QKV_N, QKV_N, 1.f);

    rmsnorm_kernel<<<T_SEQ, 256>>>(p_qkv,          qa_ln_w,  qc,  Q_LORA,  QKV_N, Q_LORA);
    rmsnorm_kernel<<<T_SEQ, 256>>>(p_qkv + Q_LORA, kva_ln_w, kvc, KV_LORA, QKV_N, KV_LORA);

    kpe_kernel<<<cdiv((long)T_SEQ * (D_ROPE/2), 256), 256>>>(positions, p_qkv, kf);

    // G3: q = qc @ w_qb — fused RoPE epilogue  (384 tiles)
    tgemm_nn<1><<<NSM_X2, blk, G_SMEM>>>(
        qc, wqb, nullptr, qf, nullptr, positions,
        QB_N / BN, QB_N, Q_LORA, Q_LORA, QB_N, 0, 1.f);

    // G4: kvup = kvc @ w_kvb — fused scatter epilogue  (512 tiles)
    tgemm_nn<2><<<NSM_X2, blk, G_SMEM>>>(
        kvc, wkvb, nullptr, kf, v, nullptr,
        KVB_N / BN, KVB_N, KV_LORA, KV_LORA, KVB_N, 0, 1.f);

    // Fused attention
    flash_kernel<<<dim3(NH, T_SEQ / 256), blk, FA_SMEM>>>(qf, kf, v, at);

    // G7: out = attn @ w_o  (640 tiles)
    tgemm_nn<0><<<NSM_X2, blk, G_SMEM>>>(
        at, wo, out, nullptr, nullptr, nullptr,
        HID / BN, HID, O_K, O_K, HID, HID, 1.f);
}

// round 17
// speedup vs baseline: 1.3387x; 1.1828x over previous
#include <cuda_runtime.h>
#include <cuda_fp16.h>
#include <math.h>
#include <stdint.h>

// ---------------- Problem constants ----------------
#define T_SEQ   2048
#define HID     5120
#define NH      16
#define D_NOPE  128
#define D_ROPE  64
#define D_V     128
#define Q_LORA  1536
#define KV_LORA 512
#define QK_HD   (D_NOPE + D_ROPE)   // 192
#define KVA_N   (KV_LORA + D_ROPE)  // 576
#define KVA_NP  640
#define QKV_N   (Q_LORA + KVA_NP)   // 2176 = 17 * 128
#define QB_N    (NH * QK_HD)        // 3072
#define KVB_N   (NH * (D_NOPE + D_V)) // 4096
#define O_K     (NH * D_V)          // 2048

static const float SCALE = 0.07216878364870322f; // 192^-0.5
#define EPS_RMS 1e-6f
#define NSM_X2  296

typedef __half f16;

// ---------------- Scratch ----------------
__device__ float g_qkv  [T_SEQ * QKV_N];

__device__ f16 g_hs    [T_SEQ * HID];
__device__ f16 g_wcomb [HID * QKV_N];
__device__ f16 g_wqb   [Q_LORA * QB_N];
__device__ f16 g_wkvb  [KV_LORA * KVB_N];
__device__ f16 g_wo    [O_K * HID];
__device__ f16 g_qc    [T_SEQ * Q_LORA];
__device__ f16 g_kvc   [T_SEQ * KV_LORA];
__device__ f16 g_qf    [(long)NH*T_SEQ*QK_HD];
__device__ f16 g_kf    [(long)NH*T_SEQ*QK_HD];
__device__ f16 g_v     [(long)NH*T_SEQ*D_V];
__device__ f16 g_at    [T_SEQ * O_K];

// ---------------- helpers ----------------
__device__ __forceinline__ uint32_t smem_u32(const void* p) {
    return (uint32_t)__cvta_generic_to_shared(p);
}
__device__ __forceinline__ void cp16(uint32_t dst, const void* src) {
    asm volatile("cp.async.cg.shared.global [%0], [%1], 16;\n" :: "r"(dst), "l"(src));
}
__device__ __forceinline__ void cp_commit() {
    asm volatile("cp.async.commit_group;\n");
}
template<int NMAX>
__device__ __forceinline__ void cp_wait() {
    asm volatile("cp.async.wait_group %0;\n" :: "n"(NMAX));
}
__device__ __forceinline__ void ldsm_x4(uint32_t addr, uint32_t r[4]) {
    asm volatile("ldmatrix.sync.aligned.m8n8.x4.shared.b16 {%0,%1,%2,%3}, [%4];"
                 : "=r"(r[0]), "=r"(r[1]), "=r"(r[2]), "=r"(r[3]) : "r"(addr));
}
__device__ __forceinline__ void ldsm_x4_t(uint32_t addr, uint32_t r[4]) {
    asm volatile("ldmatrix.sync.aligned.m8n8.x4.trans.shared.b16 {%0,%1,%2,%3}, [%4];"
                 : "=r"(r[0]), "=r"(r[1]), "=r"(r[2]), "=r"(r[3]) : "r"(addr));
}
__device__ __forceinline__ void mma_f16(float c[4], const uint32_t a[4],
                                        uint32_t b0, uint32_t b1) {
    asm volatile(
        "mma.sync.aligned.m16n8k16.row.col.f32.f16.f16.f32 "
        "{%0,%1,%2,%3}, {%4,%5,%6,%7}, {%8,%9}, {%0,%1,%2,%3};"
        : "+f"(c[0]), "+f"(c[1]), "+f"(c[2]), "+f"(c[3])
        : "r"(a[0]), "r"(a[1]), "r"(a[2]), "r"(a[3]), "r"(b0), "r"(b1));
}
__device__ __forceinline__ uint32_t pack2(f16 a, f16 b) {
    __half2 t = __halves2half2(a, b);
    return *reinterpret_cast<uint32_t*>(&t);
}

// ---------------- Persistent-tile NN tensor GEMM with fused epilogues ----------
#define BM 128
#define BN 128
#define BK 16
#define G_STG  10496
#define G_SMEM (4 * G_STG)

template<int EPI>
__global__ __launch_bounds__(256, 2)
void tgemm_nn(const f16* __restrict__ A, const f16* __restrict__ B,
              float* __restrict__ C, f16* __restrict__ O1, f16* __restrict__ O2,
              const int* __restrict__ positions,
              int tiles_n, int N, int K, int lda, int ldb, int ldc, float alpha)
{
    extern __shared__ char smem[];
    int tid  = threadIdx.x;
    int lane = tid & 31;
    int warp = tid >> 5;
    int wm   = warp >> 1;
    int wn   = warp & 1;

    int aRow = tid >> 1;
    int aKc  = (tid & 1) * 8;
    int bKr  = tid >> 4;
    int bNc  = (tid & 15) * 8;

    uint32_t sb = smem_u32(smem);
    int ntiles     = K / BK;
    int tilesTotal = tiles_n * (T_SEQ / BM);

    for (int t = blockIdx.x; t < tilesTotal; t += gridDim.x) {
        int row0 = (t / tiles_n) * BM;
        int col0 = (t % tiles_n) * BN;

        auto issue = [&](int i) {
            int k0 = i * BK;
            uint32_t stg = sb + (i & 3) * G_STG;
            cp16(stg +        (aRow * 24 + aKc) * 2, &A[(long)(row0 + aRow) * lda + k0 + aKc]);
            cp16(stg + 6144 + (bKr * 136 + bNc) * 2, &B[(long)(k0 + bKr) * ldb + col0 + bNc]);
        };

        float acc[2][8][4];
#pragma unroll
        for (int i = 0; i < 2; i++)
#pragma unroll
            for (int j = 0; j < 8; j++)
#pragma unroll
                for (int q = 0; q < 4; q++) acc[i][j][q] = 0.f;

        issue(0); cp_commit();
        if (ntiles > 1) issue(1);
        cp_commit();

        for (int i = 0; i < ntiles; i++) {
            if (i + 2 < ntiles) issue(i + 2);
            cp_commit();
            cp_wait<2>();
            __syncthreads();

            uint32_t stg = sb + (i & 3) * G_STG;
            uint32_t a_h[2][4];
#pragma unroll
            for (int mt = 0; mt < 2; mt++) {
                int r = wm * 32 + mt * 16 + (lane & 15);
                int c = (lane >> 4) * 8;
                ldsm_x4(stg + (r * 24 + c) * 2, a_h[mt]);
            }
            int rB    = lane & 15;
            int halfB = lane >> 4;
#pragma unroll
            for (int p = 0; p < 4; p++) {
                uint32_t bh[4];
                int c = wn * 64 + p * 16 + halfB * 8;
                ldsm_x4_t(stg + 6144 + (rB * 136 + c) * 2, bh);
#pragma unroll
                for (int mt = 0; mt < 2; mt++)
#pragma unroll
                    for (int j = 0; j < 2; j++)
                        mma_f16(acc[mt][2 * p + j], a_h[mt], bh[2 * j], bh[2 * j + 1]);
            }
        }
        cp_wait<0>();
        __syncthreads();

        int gid = lane >> 2, tig = lane & 3;
#pragma unroll
        for (int mt = 0; mt < 2; mt++) {
            int rb = row0 + wm * 32 + mt * 16 + gid;
#pragma unroll
            for (int nt = 0; nt < 8; nt++) {
                int c = col0 + wn * 64 + nt * 8 + tig * 2;
                if (c >= N) continue;
                float p00 = acc[mt][nt][0], p01 = acc[mt][nt][1];
                float p10 = acc[mt][nt][2], p11 = acc[mt][nt][3];
                if (EPI == 0) {
                    *reinterpret_cast<float2*>(&C[(long)rb * ldc + c]) =
                        make_float2(alpha * p00, alpha * p01);
                    *reinterpret_cast<float2*>(&C[(long)(rb + 8) * ldc + c]) =
                        make_float2(alpha * p10, alpha * p11);
                } else if (EPI == 1) {
                    int h = c / QK_HD, d = c % QK_HD;
#pragma unroll
                    for (int rr = 0; rr < 2; rr++) {
                        int r = rb + rr * 8;
                        float v0 = rr ? p10 : p00, v1 = rr ? p11 : p01;
                        long dst = ((long)h * T_SEQ + r) * QK_HD + d;
                        if (d < D_NOPE) {
                            *reinterpret_cast<uint32_t*>(&O1[dst]) =
                                pack2(__float2half_rn(v0), __float2half_rn(v1));
                        } else {
                            int i2 = (d - D_NOPE) >> 1;
                            float pos = (float)positions[r];
                            float inv = expf(-logf(10000.0f) * (2.0f * i2) / (float)D_ROPE);
                            float ang = pos * inv;
                            float cs = cosf(ang), sn = sinf(ang);
                            *reinterpret_cast<uint32_t*>(&O1[dst]) =
                                pack2(__float2half_rn(v0 * cs - v1 * sn),
                                      __float2half_rn(v1 * cs + v0 * sn));
                        }
                    }
                } else {
                    int h = c >> 8, d = c & 255;
#pragma unroll
                    for (int rr = 0; rr < 2; rr++) {
                        int r = rb + rr * 8;
                        float v0 = rr ? p10 : p00, v1 = rr ? p11 : p01;
                        uint32_t pk = pack2(__float2half_rn(v0), __float2half_rn(v1));
                        if (d < D_NOPE)
                            *reinterpret_cast<uint32_t*>(&O1[((long)h * T_SEQ + r) * QK_HD + d]) = pk;
                        else
                            *reinterpret_cast<uint32_t*>(&O2[((long)h * T_SEQ + r) * D_V + d - D_NOPE]) = pk;
                    }
                }
            }
        }
    }
}

// ---------------- Fused flash attention, 32-wide chunks ----------------
// Per j-block: 6 K-chunks (128 rows x 32 d-cols, stride 40) then
//              4 V-chunks (32 kv-rows x 128 cols, stride 136).
#define FA_QSZ   (128 * 200 * 2)       // 51200
#define FA_STG   10240                 // K chunk: 128*40*2
#define FA_SMEM  (FA_QSZ + 4 * FA_STG) // 92160

__global__ __launch_bounds__(256)
void flash_kernel(const f16* __restrict__ qf,
                  const f16* __restrict__ kf,  const f16* __restrict__ v,
                  f16* __restrict__ at)
{
    extern __shared__ char smem[];
    int h   = blockIdx.x;
    int tid = threadIdx.x;
    int lane = tid & 31;
    int wid  = tid >> 5;
    int wrow = wid * 16;

    uint32_t sQ  = smem_u32(smem);
    uint32_t stg = sQ + FA_QSZ;

    const long hT = (long)h * T_SEQ;

    auto loadQ = [&](int i0) {
#pragma unroll
        for (int it = 0; it < 12; it++) {
            int u = it * 256 + tid;
            int row = u / 24, off = (u % 24) * 8;
            cp16(sQ + (row * 200 + off) * 2, qf + (hT + i0 + row) * QK_HD + off);
        }
    };
    auto load_chunk = [&](int c) {
        uint32_t st = stg + (c & 3) * FA_STG;
        int j = c / 10, r = c % 10;
        if (r < 6) {
            int d0 = r * 32;
            int row = tid >> 1, base = (tid & 1) * 16;
            const f16* src = kf + (hT + j * 128 + row) * QK_HD + d0 + base;
            cp16(st + (row * 40 + base) * 2,     src);
            cp16(st + (row * 40 + base + 8) * 2, src + 8);
        } else {
            int q0 = (r - 6) * 32;
            int row = tid >> 3, base = (tid & 7) * 16;
            const f16* src = v + (hT + j * 128 + q0 + row) * D_V + base;
            cp16(st + (row * 136 + base) * 2,     src);
            cp16(st + (row * 136 + base + 8) * 2, src + 8);
        }
    };

    for (int rep = 0; rep < 2; rep++) {
        int iblk = rep == 0 ? blockIdx.y : (T_SEQ / 128 - 1) - blockIdx.y;
        int i0   = iblk * 128;
        int nch  = (iblk + 1) * 10;

        float s[16][4], o[16][4];
        float m0 = -1e30f, m1 = -1e30f, l0 = 0.f, l1 = 0.f;
#pragma unroll
        for (int nt = 0; nt < 16; nt++)
#pragma unroll
            for (int q = 0; q < 4; q++) o[nt][q] = 0.f;

        __syncthreads();
        loadQ(i0);
        load_chunk(0); cp_commit();
        load_chunk(1); cp_commit();

        int lr0 = wrow + (lane >> 2);
        int lr1 = lr0 + 8;

        for (int c = 0; c < nch; c++) {
            if (c + 2 < nch) load_chunk(c + 2);
            cp_commit();
            cp_wait<2>();
            __syncthreads();

            uint32_t st = stg + (c & 3) * FA_STG;
            int j = c / 10, r = c % 10;

            if (r < 6) {
                if (r == 0) {
#pragma unroll
                    for (int nt = 0; nt < 16; nt++)
#pragma unroll
                        for (int q = 0; q < 4; q++) s[nt][q] = 0.f;
                }
                int ar = wrow + (lane & 15);
                int g = lane >> 3, rr2 = lane & 7;
                int nbase = ((g >> 1) << 3) + rr2;
#pragma unroll
                for (int ks = 0; ks < 2; ks++) {
                    uint32_t a_h[4];
                    int ac = r * 32 + ks * 16 + (lane >> 4) * 8;
                    ldsm_x4(sQ + (ar * 200 + ac) * 2, a_h);
                    int cc = (g & 1) * 8 + ks * 16;
#pragma unroll
                    for (int p = 0; p < 8; p++) {
                        uint32_t bh[4];
                        ldsm_x4(st + ((p * 16 + nbase) * 40 + cc) * 2, bh);
#pragma unroll
                        for (int jj = 0; jj < 2; jj++)
                            mma_f16(s[2 * p + jj], a_h, bh[2 * jj], bh[2 * jj + 1]);
                    }
                }
                if (r == 5) {
#pragma unroll
                    for (int nt = 0; nt < 16; nt++)
#pragma unroll
                        for (int q = 0; q < 4; q++) s[nt][q] *= SCALE;
                    if (j == iblk) {
#pragma unroll
                        for (int nt = 0; nt < 16; nt++) {
                            int c0 = nt * 8 + ((lane & 3) << 1);
                            if (c0     > lr0) s[nt][0] = -1e30f;
                            if (c0 + 1 > lr0) s[nt][1] = -1e30f;
                            if (c0     > lr1) s[nt][2] = -1e30f;
                            if (c0 + 1 > lr1) s[nt][3] = -1e30f;
                        }
                    }
                    float mr0 = -1e30f, mr1 = -1e30f;
#pragma unroll
                    for (int nt = 0; nt < 16; nt++) {
                        mr0 = fmaxf(mr0, fmaxf(s[nt][0], s[nt][1]));
                        mr1 = fmaxf(mr1, fmaxf(s[nt][2], s[nt][3]));
                    }
                    mr0 = fmaxf(mr0, __shfl_xor_sync(~0u, mr0, 1));
                    mr0 = fmaxf(mr0, __shfl_xor_sync(~0u, mr0, 2));
                    mr1 = fmaxf(mr1, __shfl_xor_sync(~0u, mr1, 1));
                    mr1 = fmaxf(mr1, __shfl_xor_sync(~0u, mr1, 2));
                    float mn0 = fmaxf(m0, mr0), mn1 = fmaxf(m1, mr1);
                    float sc0 = __expf(m0 - mn0), sc1 = __expf(m1 - mn1);
                    float rs0 = 0.f, rs1 = 0.f;
#pragma unroll
                    for (int nt = 0; nt < 16; nt++) {
                        s[nt][0] = __expf(s[nt][0] - mn0); rs0 += s[nt][0];
                        s[nt][1] = __expf(s[nt][1] - mn0); rs0 += s[nt][1];
                        s[nt][2] = __expf(s[nt][2] - mn1); rs1 += s[nt][2];
                        s[nt][3] = __expf(s[nt][3] - mn1); rs1 += s[nt][3];
                    }
                    rs0 += __shfl_xor_sync(~0u, rs0, 1); rs0 += __shfl_xor_sync(~0u, rs0, 2);
                    rs1 += __shfl_xor_sync(~0u, rs1, 1); rs1 += __shfl_xor_sync(~0u, rs1, 2);
                    l0 = l0 * sc0 + rs0;  l1 = l1 * sc1 + rs1;
                    m0 = mn0; m1 = mn1;
#pragma unroll
                    for (int nt = 0; nt < 16; nt++) {
                        o[nt][0] *= sc0; o[nt][1] *= sc0;
                        o[nt][2] *= sc1; o[nt][3] *= sc1;
                    }
                }
            } else {
                int qb = (r - 6) * 2;
                int rv = lane & 15, half = lane >> 4;
#pragma unroll
                for (int ks = 0; ks < 2; ks++) {
                    int qq = qb + ks;
                    uint32_t ah[4];
                    {
                        const float* t0 = s[2 * qq];
                        const float* t1 = s[2 * qq + 1];
                        ah[0] = pack2(__float2half_rn(t0[0]), __float2half_rn(t0[1]));
                        ah[1] = pack2(__float2half_rn(t0[2]), __float2half_rn(t0[3]));
                        ah[2] = pack2(__float2half_rn(t1[0]), __float2half_rn(t1[1]));
                        ah[3] = pack2(__float2half_rn(t1[2]), __float2half_rn(t1[3]));
                    }
#pragma unroll
                    for (int pp = 0; pp < 8; pp++) {
                        uint32_t bh[4];
                        int cV = pp * 16 + half * 8;
                        ldsm_x4_t(st + ((ks * 16 + rv) * 136 + cV) * 2, bh);
#pragma unroll
                        for (int jj = 0; jj < 2; jj++)
                            mma_f16(o[2 * pp + jj], ah, bh[2 * jj], bh[2 * jj + 1]);
                    }
                }
            }
        }

        float inv0 = 1.f / l0, inv1 = 1.f / l1;
        int gr0 = i0 + lr0;
#pragma unroll
        for (int nt = 0; nt < 16; nt++) {
            int col = h * D_V + nt * 8 + ((lane & 3) << 1);
            *reinterpret_cast<uint32_t*>(&at[(long)gr0 * O_K + col]) =
                pack2(__float2half_rn(o[nt][0] * inv0), __float2half_rn(o[nt][1] * inv0));
            *reinterpret_cast<uint32_t*>(&at[(long)(gr0 + 8) * O_K + col]) =
                pack2(__float2half_rn(o[nt][2] * inv1), __float2half_rn(o[nt][3] * inv1));
        }
    }
}

// ---------------- merged flat converter ----------------
#define CVT_S0 ((long)T_SEQ * HID)
#define CVT_S1 ((long)Q_LORA * QB_N)
#define CVT_S2 ((long)KV_LORA * KVB_N)
#define CVT_S3 ((long)O_K * HID)
#define CVT_TOTAL (CVT_S0 + CVT_S1 + CVT_S2 + CVT_S3)

__global__ void cvt_all_kernel(const float* __restrict__ s0, f16* __restrict__ d0,
                               const float* __restrict__ s1, f16* __restrict__ d1,
                               const float* __restrict__ s2, f16* __restrict__ d2,
                               const float* __restrict__ s3, f16* __restrict__ d3)
{
    long i = ((long)blockIdx.x * blockDim.x + threadIdx.x) * 8;
    if (i >= CVT_TOTAL) return;
    const float* src; f16* dst; long off = i;
    if (off < CVT_S0)      { src = s0; dst = d0; }
    else if ((off -= CVT_S0) < CVT_S1) { src = s1; dst = d1; }
    else if ((off -= CVT_S1) < CVT_S2) { src = s2; dst = d2; }
    else { off -= CVT_S2; src = s3; dst = d3; }
    float4 v0 = *reinterpret_cast<const float4*>(&src[off]);
    float4 v1 = *reinterpret_cast<const float4*>(&src[off + 4]);
    uint4 o;
    o.x = pack2(__float2half_rn(v0.x), __float2half_rn(v0.y));
    o.y = pack2(__float2half_rn(v0.z), __float2half_rn(v0.w));
    o.z = pack2(__float2half_rn(v1.x), __float2half_rn(v1.y));
    o.w = pack2(__float2half_rn(v1.z), __float2half_rn(v1.w));
    *reinterpret_cast<uint4*>(&dst[off]) = o;
}
__global__ void cvt_comb_kernel(const float* __restrict__ wqa,
                                const float* __restrict__ wkva,
                                f16* __restrict__ dst)
{
    long i = (long)blockIdx.x * blockDim.x + threadIdx.x;
    if (i >= (long)HID * QKV_N) return;
    int r = (int)(i / QKV_N), c = (int)(i % QKV_N);
    float vv;
    if (c < Q_LORA)               vv = wqa[(long)r * Q_LORA + c];
    else if (c - Q_LORA < KVA_N)  vv = wkva[(long)r * KVA_N + (c - Q_LORA)];
    else                          vv = 0.f;
    dst[i] = __float2half_rn(vv);
}

// ---------------- fused norms + kpe (one block per row t) ----------------
__global__ void norms_kpe_kernel(const float* __restrict__ qkv,
                                 const float* __restrict__ qa_ln_w,
                                 const float* __restrict__ kva_ln_w,
                                 const int* __restrict__ positions,
                                 f16* __restrict__ qc, f16* __restrict__ kvc,
                                 f16* __restrict__ kf)
{
    int t = blockIdx.x;
    const float* row = qkv + (long)t * QKV_N;
    __shared__ float sh[33];
    int lane = threadIdx.x & 31, wrp = threadIdx.x >> 5;

    auto reduce_sum = [&](float ss) -> float {
#pragma unroll
        for (int o = 16; o; o >>= 1) ss += __shfl_xor_sync(~0u, ss, o);
        if (lane == 0) sh[wrp] = ss;
        __syncthreads();
        if (wrp == 0) {
            float v = (lane < (blockDim.x >> 5)) ? sh[lane] : 0.f;
#pragma unroll
            for (int o = 16; o; o >>= 1) v += __shfl_xor_sync(~0u, v, o);
            if (lane == 0) sh[32] = v;
        }
        __syncthreads();
        float r = sh[32];
        __syncthreads();
        return r;
    };

    // norm 1: qa (cols 0..1535)
    float ss = 0.f;
    for (int i = threadIdx.x; i < Q_LORA; i += blockDim.x) {
        float v = row[i]; ss += v * v;
    }
    float r1 = rsqrtf(reduce_sum(ss) / (float)Q_LORA + EPS_RMS);
    for (int i = threadIdx.x; i < Q_LORA; i += blockDim.x)
        qc[(long)t * Q_LORA + i] = __float2half_rn(row[i] * r1 * qa_ln_w[i]);

    // norm 2: kv (cols 1536..2047)
    ss = 0.f;
    for (int i = threadIdx.x; i < KV_LORA; i += blockDim.x) {
        float v = row[Q_LORA + i]; ss += v * v;
    }
    float r2 = rsqrtf(reduce_sum(ss) / (float)KV_LORA + EPS_RMS);
    for (int i = threadIdx.x; i < KV_LORA; i += blockDim.x)
        kvc[(long)t * KV_LORA + i] = __float2half_rn(row[Q_LORA + i] * r2 * kva_ln_w[i]);

    // kpe: cols 2048..2111 (32 pairs)
    if (threadIdx.x < 32) {
        int k = threadIdx.x;
        float pos = (float)positions[t];
        float inv = expf(-logf(10000.0f) * (2.0f * k) / (float)D_ROPE);
        float ang = pos * inv;
        float cs = cosf(ang), sn = sinf(ang);
        float x1 = row[Q_LORA + KV_LORA + 2 * k];
        float x2 = row[Q_LORA + KV_LORA + 2 * k + 1];
        uint32_t pk = pack2(__float2half_rn(x1 * cs - x2 * sn),
                            __float2half_rn(x2 * cs + x1 * sn));
#pragma unroll
        for (int h = 0; h < NH; h++)
            *reinterpret_cast<uint32_t*>(&kf[((long)h * T_SEQ + t) * QK_HD + D_NOPE + 2 * k]) = pk;
    }
}

// ---------------- Launch ----------------
extern "C" void kernel_launch(void* const* d_in, const int* in_sizes, int n_in,
                              void* d_out, int out_size)
{
    const int*   positions = (const int*)  d_in[0];
    const float* hs        = (const float*)d_in[1];
    const float* w_qa      = (const float*)d_in[2];
    const float* qa_ln_w   = (const float*)d_in[3];
    const float* w_qb      = (const float*)d_in[4];
    const float* w_kva     = (const float*)d_in[5];
    const float* kva_ln_w  = (const float*)d_in[6];
    const float* w_kvb     = (const float*)d_in[7];
    const float* w_o       = (const float*)d_in[8];
    float* out = (float*)d_out;

    float *p_qkv;
    f16 *phs, *wcomb, *wqb, *wkvb, *wo;
    f16 *qc, *kvc, *qf, *kf, *v, *at;

    cudaGetSymbolAddress((void**)&p_qkv,  g_qkv);
    cudaGetSymbolAddress((void**)&phs,    g_hs);
    cudaGetSymbolAddress((void**)&wcomb,  g_wcomb);
    cudaGetSymbolAddress((void**)&wqb,    g_wqb);
    cudaGetSymbolAddress((void**)&wkvb,   g_wkvb);
    cudaGetSymbolAddress((void**)&wo,     g_wo);
    cudaGetSymbolAddress((void**)&qc,     g_qc);
    cudaGetSymbolAddress((void**)&kvc,    g_kvc);
    cudaGetSymbolAddress((void**)&qf,     g_qf);
    cudaGetSymbolAddress((void**)&kf,     g_kf);
    cudaGetSymbolAddress((void**)&v,      g_v);
    cudaGetSymbolAddress((void**)&at,     g_at);

    cudaFuncSetAttribute(tgemm_nn<0>,  cudaFuncAttributeMaxDynamicSharedMemorySize, G_SMEM);
    cudaFuncSetAttribute(tgemm_nn<1>,  cudaFuncAttributeMaxDynamicSharedMemorySize, G_SMEM);
    cudaFuncSetAttribute(tgemm_nn<2>,  cudaFuncAttributeMaxDynamicSharedMemorySize, G_SMEM);
    cudaFuncSetAttribute(flash_kernel, cudaFuncAttributeMaxDynamicSharedMemorySize, FA_SMEM);

    dim3 blk(256);
    auto cdiv = [](long a, long b) { return (int)((a + b - 1) / b); };

    cvt_all_kernel<<<cdiv(CVT_TOTAL / 8, 256), 256>>>(hs, phs, w_qb, wqb, w_kvb, wkvb, w_o, wo);
    cvt_comb_kernel<<<cdiv((long)HID * QKV_N, 256), 256>>>(w_qa, w_kva, wcomb);

    // G1+G2 merged
    tgemm_nn<0><<<NSM_X2, blk, G_SMEM>>>(
        phs, wcomb, p_qkv, nullptr, nullptr, nullptr,
        QKV_N / BN, QKV_N, HID, HID, QKV_N, QKV_N, 1.f);

    // fused rmsnorm x2 + kpe
    norms_kpe_kernel<<<T_SEQ, 256>>>(p_qkv, qa_ln_w, kva_ln_w, positions, qc, kvc, kf);

    // G3: fused RoPE epilogue
    tgemm_nn<1><<<NSM_X2, blk, G_SMEM>>>(
        qc, wqb, nullptr, qf, nullptr, positions,
        QB_N / BN, QB_N, Q_LORA, Q_LORA, QB_N, 0, 1.f);

    // G4: fused scatter epilogue
    tgemm_nn<2><<<NSM_X2, blk, G_SMEM>>>(
        kvc, wkvb, nullptr, kf, v, nullptr,
        KVB_N / BN, KVB_N, KV_LORA, KV_LORA, KVB_N, 0, 1.f);

    // Fused attention (32-wide chunks)
    flash_kernel<<<dim3(NH, T_SEQ / 256), blk, FA_SMEM>>>(qf, kf, v, at);

    // G7
    tgemm_nn<0><<<NSM_X2, blk, G_SMEM>>>(
        at, wo, out, nullptr, nullptr, nullptr,
        HID / BN, HID, O_K, O_K, HID, HID, 1.f);
}